// round 13
// baseline (speedup 1.0000x reference)
#include <cuda_runtime.h>
#include <cuda_fp16.h>
#include <cstdint>

#define BB    32
#define KK    1024
#define CC    256
#define PP    256
#define NSAMP 16
#define NROWS (BB*PP*NSAMP)   // 131072
#define NG    (BB*PP)         // 8192
#define HID   128
#define OUTC  119

// output segment offsets (floats): obj, center, hs, hrn, hr, ss, srn, sr, sem, new_xyz, inds
#define O_OBJ    0
#define O_CENTER 16384
#define O_HS     40960
#define O_HRN    139264
#define O_HR     237568
#define O_SS     335872
#define O_SRN    483328
#define O_SR     925696
#define O_SEM    1368064
#define O_NEWXYZ 1515520
#define O_INDS   1540096

// ---------------- scratch ----------------
__device__ int   g_inds[NG];
__device__ float g_newxyz[NG*3];
__device__ int   g_idx[NROWS];
__device__ __align__(16) float g_feat[NG*HID];
// fp16 MLP weights in m16n8k16 B-fragment layout (word = uint32 = 2 halfs)
__device__ __align__(16) uint32_t g_w0h[17*16*32*2];  // K=272 (k 0..255=feats, 256..258=xyz, rest 0)
__device__ __align__(16) uint32_t g_w1h[8*16*32*2];
__device__ __align__(16) uint32_t g_w2h[8*16*32*2];
// tf32 FC weights, hi + lo residual, m16n8k8 B-fragment layout
__device__ __align__(16) float g_fw1f[16384], g_fl1f[16384];
__device__ __align__(16) float g_fw2f[16384], g_fl2f[16384];
__device__ __align__(16) float g_fw3f[16384], g_fl3f[16384];  // head, N padded 119->128

__device__ __forceinline__ float tf32r(float v) {
    float o;
    asm("cvt.rna.tf32.f32 %0, %1;" : "=f"(o) : "f"(v));
    return o;
}
__device__ __forceinline__ uint32_t packh2(float a, float b) {
    __half2 h = __floats2half2_rn(a, b);
    return *(uint32_t*)&h;
}
__device__ __forceinline__ uint32_t redux_max_u32(uint32_t v) {
    uint32_t r;
    asm volatile("redux.sync.max.u32 %0, %1, 0xffffffff;" : "=r"(r) : "r"(v));
    return r;
}
__device__ __forceinline__ uint32_t redux_min_u32(uint32_t v) {
    uint32_t r;
    asm volatile("redux.sync.min.u32 %0, %1, 0xffffffff;" : "=r"(r) : "r"(v));
    return r;
}

// fp16 mma m16n8k16
__device__ __forceinline__ void mma16(float c[4], uint32_t a0, uint32_t a1, uint32_t a2, uint32_t a3,
                                      uint32_t b0, uint32_t b1) {
    asm volatile(
        "mma.sync.aligned.m16n8k16.row.col.f32.f16.f16.f32 "
        "{%0,%1,%2,%3}, {%4,%5,%6,%7}, {%8,%9}, {%0,%1,%2,%3};\n"
        : "+f"(c[0]), "+f"(c[1]), "+f"(c[2]), "+f"(c[3])
        : "r"(a0), "r"(a1), "r"(a2), "r"(a3), "r"(b0), "r"(b1));
}
// tf32 mma m16n8k8
__device__ __forceinline__ void mma8(float c[4], const float a[4], float b0, float b1) {
    asm volatile(
        "mma.sync.aligned.m16n8k8.row.col.f32.tf32.tf32.f32 "
        "{%0,%1,%2,%3}, {%4,%5,%6,%7}, {%8,%9}, {%0,%1,%2,%3};\n"
        : "+f"(c[0]), "+f"(c[1]), "+f"(c[2]), "+f"(c[3])
        : "r"(__float_as_uint(a[0])), "r"(__float_as_uint(a[1])),
          "r"(__float_as_uint(a[2])), "r"(__float_as_uint(a[3])),
          "r"(__float_as_uint(b0)), "r"(__float_as_uint(b1)));
}

// tf32 B-fragment scatter (k8 tiles)
__device__ __forceinline__ void bfrag_store(float* dst, int k, int n, float v) {
    int kt = k >> 3, kin = k & 7, ntl = n >> 3, gq = n & 7;
    int lane = gq*4 + (kin & 3), slot = kin >> 2;
    dst[((kt*16 + ntl)*32 + lane)*2 + slot] = v;
}
// fp16 B-fragment scatter (k16 tiles); writes one half
__device__ __forceinline__ void bfrag16_store(uint32_t* dst, int k, int n, __half v) {
    int kt = k >> 4, kin = k & 15, ntl = n >> 3, gq = n & 7;
    int lane = gq*4 + ((kin >> 1) & 3), reg = kin >> 3;
    __half* p = (__half*)&dst[((kt*16 + ntl)*32 + lane)*2 + reg];
    p[k & 1] = v;
}

// fp16 A-fragment pair store
__device__ __forceinline__ void a16pair(uint32_t* frag_mbase, int grp, int rowhi, int kp, uint32_t packed) {
    frag_mbase[(grp*4 + (kp & 3))*4 + ((kp & 4) ? 2 : 0) + rowhi] = packed;
}

// ---------------- FPS + ball query + tail (blocks 0..31) + weight prep (32..147) ----------------
__global__ __launch_bounds__(128)
void fps_prep_kernel(const float* __restrict__ xyz,
                     const float* __restrict__ w0,
                     const float* __restrict__ wm1,
                     const float* __restrict__ wm2,
                     const float* __restrict__ w1,
                     const float* __restrict__ w2,
                     const float* __restrict__ w3,
                     float* __restrict__ out) {
    __shared__ float4 sp4[KK];
    __shared__ uint2  swc[2][4];   // [parity][warp] = (dist bits, global idx)
    __shared__ short  s_sel[PP];

    if (blockIdx.x >= 32) {
        // ---- weight prep: 116 blocks x 128 threads over 116736 elements ----
        for (int i = (blockIdx.x - 32) * 128 + threadIdx.x; i < 116736; i += 116 * 128) {
            if (i < 34816) {             // w0h: K permuted+padded to 272
                int kd = i >> 7, n = i & 127;
                float v = 0.0f;
                if (kd < 256)      v = w0[(size_t)(kd + 3)*128 + n];
                else if (kd < 259) v = w0[(size_t)(kd - 256)*128 + n];
                bfrag16_store(g_w0h, kd, n, __float2half_rn(v));
            } else if (i < 51200) {
                int j = i - 34816; int k = j >> 7, n = j & 127;
                bfrag16_store(g_w1h, k, n, __float2half_rn(wm1[j]));
            } else if (i < 67584) {
                int j = i - 51200; int k = j >> 7, n = j & 127;
                bfrag16_store(g_w2h, k, n, __float2half_rn(wm2[j]));
            } else if (i < 83968) {
                int j = i - 67584; int k = j >> 7, n = j & 127;
                float w = w1[j]; float hi = tf32r(w);
                bfrag_store(g_fw1f, k, n, hi);
                bfrag_store(g_fl1f, k, n, tf32r(w - hi));
            } else if (i < 100352) {
                int j = i - 83968; int k = j >> 7, n = j & 127;
                float w = w2[j]; float hi = tf32r(w);
                bfrag_store(g_fw2f, k, n, hi);
                bfrag_store(g_fl2f, k, n, tf32r(w - hi));
            } else {
                int j = i - 100352; int k = j >> 7, n = j & 127;
                float w = (n < OUTC) ? w3[(size_t)k*OUTC + n] : 0.0f;
                float hi = tf32r(w);
                bfrag_store(g_fw3f, k, n, hi);
                bfrag_store(g_fl3f, k, n, tf32r(w - hi));
            }
        }
        return;
    }

    const int b = blockIdx.x;
    const int t = threadIdx.x;      // 0..127
    const int w = t >> 5, lane = t & 31;
    const float* xb = xyz + (size_t)b * KK * 3;

    for (int i = t; i < KK; i += 128)
        sp4[i] = make_float4(xb[i*3+0], xb[i*3+1], xb[i*3+2], 0.0f);
    if (t == 0) s_sel[0] = 0;
    __syncthreads();

    // this thread owns points t*8 .. t*8+7 (registers)
    float px[8], py[8], pz[8], dist[8];
    #pragma unroll
    for (int q = 0; q < 8; q++) {
        float4 p = sp4[t*8 + q];
        px[q] = p.x; py[q] = p.y; pz[q] = p.z;
        dist[q] = 1e10f;
    }
    float4 lp = sp4[0];

    for (int it = 1; it < PP; it++) {
        float best = -1.0f; int bidx = 0;
        #pragma unroll
        for (int q = 0; q < 8; q++) {
            float dx = px[q] - lp.x, dy = py[q] - lp.y, dz = pz[q] - lp.z;
            float d = fmaf(dz, dz, fmaf(dy, dy, dx*dx));
            d = fminf(dist[q], d);
            dist[q] = d;
            if (d > best) { best = d; bidx = t*8 + q; }   // strict > keeps first q
        }
        uint32_t mv = redux_max_u32(__float_as_uint(best));
        uint32_t cand = (__float_as_uint(best) == mv) ? (uint32_t)bidx : 0xFFFFFFFFu;
        uint32_t widx = redux_min_u32(cand);

        if (lane == 0) swc[it & 1][w] = make_uint2(mv, widx);
        __syncthreads();

        // every thread resolves the block winner itself
        uint2 c0 = swc[it & 1][0];
        uint32_t bv = c0.x, bi = c0.y;
        #pragma unroll
        for (int ww = 1; ww < 4; ww++) {
            uint2 c = swc[it & 1][ww];
            if (c.x > bv || (c.x == bv && c.y < bi)) { bv = c.x; bi = c.y; }
        }
        lp = sp4[bi];
        if (t == 0) s_sel[it] = (short)bi;
    }
    __syncthreads();

    // ---- final writes: inds + new_xyz (scratch + output) ----
    for (int e = t; e < PP; e += 128) {
        int ci = s_sel[e];
        g_inds[b*PP + e] = ci;
        out[O_INDS + b*PP + e] = (float)ci;
        float4 c = sp4[ci];
        int base = (b*PP + e)*3;
        g_newxyz[base+0] = c.x; g_newxyz[base+1] = c.y; g_newxyz[base+2] = c.z;
        out[O_NEWXYZ + base + 0] = c.x;
        out[O_NEWXYZ + base + 1] = c.y;
        out[O_NEWXYZ + base + 2] = c.z;
    }

    // ---- fused ball query: 128 threads, 2 queries each ----
    for (int qq = t; qq < PP; qq += 128) {
        float4 qp = sp4[s_sel[qq]];
        int buf[NSAMP]; int cnt = 0;
        #pragma unroll 4
        for (int j = 0; j < KK; j++) {
            float4 p = sp4[j];
            float dx = qp.x - p.x, dy = qp.y - p.y, dz = qp.z - p.z;
            float d = fmaf(dz, dz, fmaf(dy, dy, dx*dx));
            if (d < 0.09f) { if (cnt < NSAMP) buf[cnt] = j; cnt++; }
        }
        if (cnt == 0) { for (int s = 0; s < NSAMP; s++) buf[s] = KK - 1; }
        else { int c = cnt < NSAMP ? cnt : NSAMP; for (int s = c; s < NSAMP; s++) buf[s] = buf[0]; }
        const int gp = b*PP + qq;
        #pragma unroll
        for (int s = 0; s < NSAMP; s++) g_idx[gp*NSAMP + s] = buf[s];
    }
}

// ---------------- fused layer0+1+2+maxpool (fp16 mma, M=256, 512 threads) ----------------
// smem word map (uint32, total 41984 words = 164KB):
//   B0  [0, 17408)        — dead after L0; A_L1 overlays [0, 16384)
//   B2  [17408, 25600)
//   B1  [25600, 33792)    — dead after L1; A_L2 overlays [25600, 41984) (also covers Ach)
//   Ach [33792, 37888)    — gather double-buffer (2 x 2048), dead after L0
__global__ __launch_bounds__(512, 1)
void fused_mlp_kernel(const float* __restrict__ xyz,
                      const float* __restrict__ feats,
                      const float* __restrict__ b0, const float* __restrict__ g0, const float* __restrict__ e0,
                      const float* __restrict__ b1, const float* __restrict__ g1, const float* __restrict__ e1,
                      const float* __restrict__ b2, const float* __restrict__ g2, const float* __restrict__ e2) {
    extern __shared__ uint32_t smw[];
    __shared__ float sg[3][128], sb[3][128], se[3][128];
    __shared__ int   sj[256];
    __shared__ float sg3s[256][3];

    const int tid = threadIdx.x, lane = tid & 31, wid = tid >> 5;
    const int warp_m = wid >> 1, warp_n = wid & 1;   // warp_m 0..7
    const int grp = lane >> 2, tig = lane & 3;
    const int tile = blockIdx.x, row0 = tile * 256;

    if (tid < 128) {
        sg[0][tid] = g0[tid]; sb[0][tid] = b0[tid]; se[0][tid] = e0[tid];
        sg[1][tid] = g1[tid]; sb[1][tid] = b1[tid]; se[1][tid] = e1[tid];
        sg[2][tid] = g2[tid]; sb[2][tid] = b2[tid]; se[2][tid] = e2[tid];
    }
    if (tid < 256) {
        int grow = row0 + tid;
        int bb = grow >> 12;
        int p = (grow & 4095) >> 4;
        int j = g_idx[grow];
        sj[tid] = j;
        int gp = bb * PP + p;
        #pragma unroll
        for (int d = 0; d < 3; d++)
            sg3s[tid][d] = __fdiv_rn(xyz[(size_t)(bb*KK + j)*3 + d] - g_newxyz[gp*3 + d], 0.3f);
    }
    __syncthreads();   // sj ready

    // stage all B (fp16): B0 4352 uint4, B2/B1 2048 each
    {
        const uint4* s0 = (const uint4*)g_w0h;
        uint4* d0 = (uint4*)smw;
        for (int q = tid; q < 4352; q += 512) d0[q] = s0[q];
        const uint4* s2 = (const uint4*)g_w2h;
        uint4* d2 = (uint4*)(smw + 17408);
        for (int q = tid; q < 2048; q += 512) d2[q] = s2[q];
        const uint4* s1 = (const uint4*)g_w1h;
        uint4* d1 = (uint4*)(smw + 25600);
        for (int q = tid; q < 2048; q += 512) d1[q] = s1[q];
    }

    const int ar = tid >> 1, h = tid & 1;   // ar 0..255
    const float4* frow4 = (const float4*)(feats + (size_t)((row0 >> 12) * KK + sj[ar]) * CC);
    const int m_tile_f = ar >> 4;           // 0..15
    const int R = ar & 15;
    const int grpa = R & 7;
    const int rowhi = R >> 3;

    // fill gather chunk kt=0 (Ach buffer 0)
    {
        uint32_t* Am = smw + 33792 + m_tile_f*128;
        float4 f0 = frow4[h*2], f1 = frow4[h*2 + 1];
        a16pair(Am, grpa, rowhi, h*4+0, packh2(f0.x, f0.y));
        a16pair(Am, grpa, rowhi, h*4+1, packh2(f0.z, f0.w));
        a16pair(Am, grpa, rowhi, h*4+2, packh2(f1.x, f1.y));
        a16pair(Am, grpa, rowhi, h*4+3, packh2(f1.z, f1.w));
    }
    __syncthreads();

    float acc[2][8][4];
    #pragma unroll
    for (int mt = 0; mt < 2; mt++)
        #pragma unroll
        for (int nt = 0; nt < 8; nt++)
            #pragma unroll
            for (int q = 0; q < 4; q++) acc[mt][nt][q] = 0.0f;

    // ---- layer 0: 17 k16-tiles, double-buffered gather ----
    for (int kt = 0; kt < 17; kt++) {
        float4 n0, n1;
        if (kt < 15) { n0 = frow4[(kt+1)*4 + h*2]; n1 = frow4[(kt+1)*4 + h*2 + 1]; }

        const uint32_t* Ac = smw + 33792 + (kt & 1)*2048;
        #pragma unroll
        for (int mt = 0; mt < 2; mt++) {
            uint4 av = *(const uint4*)&Ac[(warp_m*2 + mt)*128 + lane*4];
            #pragma unroll
            for (int nt = 0; nt < 8; nt++) {
                uint2 bv = *(const uint2*)&smw[kt*1024 + (warp_n*8 + nt)*64 + lane*2];
                mma16(acc[mt][nt], av.x, av.y, av.z, av.w, bv.x, bv.y);
            }
        }

        if (kt < 16) {
            uint32_t* Am = smw + 33792 + ((kt+1) & 1)*2048 + m_tile_f*128;
            if (kt < 15) {
                a16pair(Am, grpa, rowhi, h*4+0, packh2(n0.x, n0.y));
                a16pair(Am, grpa, rowhi, h*4+1, packh2(n0.z, n0.w));
                a16pair(Am, grpa, rowhi, h*4+2, packh2(n1.x, n1.y));
                a16pair(Am, grpa, rowhi, h*4+3, packh2(n1.z, n1.w));
            } else {
                uint32_t p0 = 0, p1 = 0;
                if (h == 0) {
                    p0 = packh2(sg3s[ar][0], sg3s[ar][1]);
                    p1 = packh2(sg3s[ar][2], 0.0f);
                }
                a16pair(Am, grpa, rowhi, h*4+0, p0);
                a16pair(Am, grpa, rowhi, h*4+1, p1);
                a16pair(Am, grpa, rowhi, h*4+2, 0u);
                a16pair(Am, grpa, rowhi, h*4+3, 0u);
            }
        }
        __syncthreads();
    }

    // epilogue helper: next layer's fp16 A-frag into dstw, zero acc
    auto epi16 = [&](uint32_t* dstw, int li) {
        #pragma unroll
        for (int mt = 0; mt < 2; mt++) {
            #pragma unroll
            for (int nt = 0; nt < 8; nt++) {
                int c = warp_n*64 + nt*8 + tig*2;
                float ga = sg[li][c], gb = sg[li][c+1];
                float ba = sb[li][c], bbv = sb[li][c+1];
                float ea = se[li][c], eb = se[li][c+1];
                float v0 = fmaxf(fmaf(ga, acc[mt][nt][0] + ba, ea), 0.0f);
                float v1 = fmaxf(fmaf(gb, acc[mt][nt][1] + bbv, eb), 0.0f);
                float v2 = fmaxf(fmaf(ga, acc[mt][nt][2] + ba, ea), 0.0f);
                float v3 = fmaxf(fmaf(gb, acc[mt][nt][3] + bbv, eb), 0.0f);
                int k_tile = warp_n*4 + (nt >> 1);
                uint32_t* p = dstw + ((warp_m*2 + mt)*8 + k_tile)*128 + (grp*4 + tig)*4 + (nt & 1)*2;
                *(uint2*)p = make_uint2(packh2(v0, v1), packh2(v2, v3));
                acc[mt][nt][0] = 0.f; acc[mt][nt][1] = 0.f; acc[mt][nt][2] = 0.f; acc[mt][nt][3] = 0.f;
            }
        }
    };

    epi16(smw, 0);            // A_L1 over B0 region [0,16384)
    __syncthreads();

    // ---- layer 1: A_L1 @ smw, B1 @ smw+25600 ----
    #pragma unroll
    for (int ks = 0; ks < 8; ks++) {
        #pragma unroll
        for (int mt = 0; mt < 2; mt++) {
            uint4 av = *(const uint4*)&smw[((warp_m*2 + mt)*8 + ks)*128 + lane*4];
            #pragma unroll
            for (int nt = 0; nt < 8; nt++) {
                uint2 bv = *(const uint2*)&smw[25600 + ks*1024 + (warp_n*8 + nt)*64 + lane*2];
                mma16(acc[mt][nt], av.x, av.y, av.z, av.w, bv.x, bv.y);
            }
        }
    }
    __syncthreads();          // all warps done reading B1/A_L1
    epi16(smw + 25600, 1);    // A_L2 over B1+Ach [25600,41984)
    __syncthreads();

    // ---- layer 2: A_L2 @ smw+25600, B2 @ smw+17408 ----
    #pragma unroll
    for (int ks = 0; ks < 8; ks++) {
        #pragma unroll
        for (int mt = 0; mt < 2; mt++) {
            uint4 av = *(const uint4*)&smw[25600 + ((warp_m*2 + mt)*8 + ks)*128 + lane*4];
            #pragma unroll
            for (int nt = 0; nt < 8; nt++) {
                uint2 bv = *(const uint2*)&smw[17408 + ks*1024 + (warp_n*8 + nt)*64 + lane*2];
                mma16(acc[mt][nt], av.x, av.y, av.z, av.w, bv.x, bv.y);
            }
        }
    }

    // ---- maxpool epilogue (16 groups of 16 rows) ----
    #pragma unroll
    for (int mt = 0; mt < 2; mt++) {
        int gidx = tile*16 + warp_m*2 + mt;
        #pragma unroll
        for (int nt = 0; nt < 8; nt++) {
            int c = warp_n*64 + nt*8 + tig*2;
            float ga = sg[2][c], gb = sg[2][c+1];
            float ba = sb[2][c], bbv = sb[2][c+1];
            float ea = se[2][c], eb = se[2][c+1];
            float v0 = fmaxf(fmaf(ga, acc[mt][nt][0] + ba, ea), 0.0f);
            float v1 = fmaxf(fmaf(gb, acc[mt][nt][1] + bbv, eb), 0.0f);
            float v2 = fmaxf(fmaf(ga, acc[mt][nt][2] + ba, ea), 0.0f);
            float v3 = fmaxf(fmaf(gb, acc[mt][nt][3] + bbv, eb), 0.0f);
            float mA = fmaxf(v0, v2), mB = fmaxf(v1, v3);
            #pragma unroll
            for (int o = 4; o < 32; o <<= 1) {
                mA = fmaxf(mA, __shfl_xor_sync(0xffffffffu, mA, o));
                mB = fmaxf(mB, __shfl_xor_sync(0xffffffffu, mB, o));
            }
            if (grp == 0) {
                g_feat[(size_t)gidx*128 + c]     = mA;
                g_feat[(size_t)gidx*128 + c + 1] = mB;
            }
        }
    }
}

// ---------------- FC helpers (tf32 path) ----------------
__device__ __forceinline__ void afrag_sts4_fc(float* A, int m_tile, int kl0,
                                              int laneRow, int slotR, float4 v) {
    int ktl = kl0 >> 3;
    int kin0 = kl0 & 7;
    int base = (m_tile*16 + ktl)*128 + laneRow*16 + slotR + ((kin0 < 4) ? 0 : 2);
    A[base + 0]  = tf32r(v.x);
    A[base + 4]  = tf32r(v.y);
    A[base + 8]  = tf32r(v.z);
    A[base + 12] = tf32r(v.w);
}

// M=64 tile GEMM: each warp owns m_tile = warp_m (0..3), N-half = warp_n
__device__ __forceinline__ void mma_64(const float* Af, const float* Bst,
                                       float acc[8][4],
                                       int warp_m, int warp_n, int lane) {
    #pragma unroll
    for (int ks = 0; ks < 16; ks++) {
        float4 a0 = *(const float4*)&Af[(warp_m*16 + ks)*128 + lane*4];
        float2 bv[8];
        #pragma unroll
        for (int nt = 0; nt < 8; nt++)
            bv[nt] = *(const float2*)&Bst[((ks*16 + warp_n*8 + nt)*32 + lane)*2];
        #pragma unroll
        for (int nt = 0; nt < 8; nt++)
            mma8(acc[nt], (const float*)&a0, bv[nt].x, bv[nt].y);
    }
}

// ---------------- fused FC1+FC2+head, error-compensated tf32 (M=64, grid=128) ----------------
// smem floats: A_hi [0,8192), A_lo [8192,16384), Bst [16384,32768)  (128KB)
__global__ __launch_bounds__(256)
void fused_fc_kernel(const float* __restrict__ b1, const float* __restrict__ g1, const float* __restrict__ e1,
                     const float* __restrict__ b2, const float* __restrict__ g2, const float* __restrict__ e2,
                     const float* __restrict__ b3, const float* __restrict__ msz,
                     float* __restrict__ out) {
    extern __shared__ float sm[];
    float* A_hi = sm;
    float* A_lo = sm + 8192;
    float* Bst  = sm + 16384;
    __shared__ float sg1[128], sb1[128], se1[128], sg2[128], sb2[128], se2[128];
    __shared__ float sb3[128], sms[54];

    const int tid = threadIdx.x, lane = tid & 31, wid = tid >> 5;
    const int warp_m = wid >> 1, warp_n = wid & 1;   // warp_m 0..3 = m_tile
    const int grp = lane >> 2, tig = lane & 3;
    const int row0 = blockIdx.x * 64;

    if (tid < 128) {
        sg1[tid] = g1[tid]; sb1[tid] = b1[tid]; se1[tid] = e1[tid];
        sg2[tid] = g2[tid]; sb2[tid] = b2[tid]; se2[tid] = e2[tid];
        sb3[tid] = (tid < OUTC) ? b3[tid] : 0.0f;
    } else if (tid < 182) {
        sms[tid - 128] = msz[tid - 128];
    }

    // fill A_hi / A_lo from g_feat: 64 rows, 4 threads/row (32 cols each)
    const int ar = tid >> 2, h = tid & 3;
    const int m_tile_f = ar >> 4;
    const int R = ar & 15;
    const int laneRow = R & 7;
    const int slotR = (R < 8) ? 0 : 1;
    {
        const float4* frow4 = (const float4*)(g_feat + (size_t)(row0 + ar) * 128);
        #pragma unroll
        for (int j = 0; j < 8; j++) {
            float4 v = frow4[h*8 + j];
            float4 hi = make_float4(tf32r(v.x), tf32r(v.y), tf32r(v.z), tf32r(v.w));
            float4 lo = make_float4(v.x - hi.x, v.y - hi.y, v.z - hi.z, v.w - hi.w);
            afrag_sts4_fc(A_hi, m_tile_f, h*32 + j*4, laneRow, slotR, hi);
            afrag_sts4_fc(A_lo, m_tile_f, h*32 + j*4, laneRow, slotR, lo);
        }
    }

    float acc[8][4];
    #pragma unroll
    for (int nt = 0; nt < 8; nt++)
        #pragma unroll
        for (int q = 0; q < 4; q++) acc[nt][q] = 0.0f;

    auto stage = [&](const float* src) {
        const float4* s = (const float4*)src;
        float4* d = (float4*)Bst;
        #pragma unroll
        for (int q = 0; q < 16; q++) d[tid + q*256] = s[tid + q*256];
    };
    // compensated epilogue: relu6 affine -> hi/lo in place
    auto epi_hilo = [&](const float* sgp, const float* sbp, const float* sep) {
        const int la0 = grp*4 + ((2*tig) & 3);
        const int slot_hi = (tig < 2) ? 0 : 2;
        #pragma unroll
        for (int nt = 0; nt < 8; nt++) {
            int c = warp_n*64 + nt*8 + tig*2;
            float ga = sgp[c], gb = sgp[c+1], ba = sbp[c], bbv = sbp[c+1], ea = sep[c], eb = sep[c+1];
            float v0 = fminf(fmaxf(fmaf(ga, acc[nt][0] + ba, ea), 0.0f), 6.0f);
            float v1 = fminf(fmaxf(fmaf(gb, acc[nt][1] + bbv, eb), 0.0f), 6.0f);
            float v2 = fminf(fmaxf(fmaf(ga, acc[nt][2] + ba, ea), 0.0f), 6.0f);
            float v3 = fminf(fmaxf(fmaf(gb, acc[nt][3] + bbv, eb), 0.0f), 6.0f);
            float h0 = tf32r(v0), h1 = tf32r(v1), h2 = tf32r(v2), h3 = tf32r(v3);
            int kt = warp_n*8 + nt;
            float* pH = A_hi + (warp_m*16 + kt)*128 + la0*4 + slot_hi;
            float* pL = A_lo + (warp_m*16 + kt)*128 + la0*4 + slot_hi;
            *(float2*)pH       = make_float2(h0, h2);
            *(float2*)(pH + 4) = make_float2(h1, h3);
            *(float2*)pL       = make_float2(tf32r(v0 - h0), tf32r(v2 - h2));
            *(float2*)(pL + 4) = make_float2(tf32r(v1 - h1), tf32r(v3 - h3));
            acc[nt][0] = 0.f; acc[nt][1] = 0.f; acc[nt][2] = 0.f; acc[nt][3] = 0.f;
        }
    };

    // ---- FC1 ----
    stage(g_fw1f);
    __syncthreads();
    mma_64(A_hi, Bst, acc, warp_m, warp_n, lane);
    mma_64(A_lo, Bst, acc, warp_m, warp_n, lane);
    __syncthreads();
    stage(g_fl1f);
    __syncthreads();
    mma_64(A_hi, Bst, acc, warp_m, warp_n, lane);
    __syncthreads();
    epi_hilo(sg1, sb1, se1);
    __syncthreads();

    // ---- FC2 ----
    stage(g_fw2f);
    __syncthreads();
    mma_64(A_hi, Bst, acc, warp_m, warp_n, lane);
    mma_64(A_lo, Bst, acc, warp_m, warp_n, lane);
    __syncthreads();
    stage(g_fl2f);
    __syncthreads();
    mma_64(A_hi, Bst, acc, warp_m, warp_n, lane);
    __syncthreads();
    epi_hilo(sg2, sb2, se2);
    __syncthreads();

    // ---- head ----
    stage(g_fw3f);
    __syncthreads();
    mma_64(A_hi, Bst, acc, warp_m, warp_n, lane);
    mma_64(A_lo, Bst, acc, warp_m, warp_n, lane);
    __syncthreads();
    stage(g_fl3f);
    __syncthreads();
    mma_64(A_hi, Bst, acc, warp_m, warp_n, lane);

    // head scatter from accumulator frags
    const float HRS = (float)(3.14159265359 / 12.0);
    {
        int rA = row0 + warp_m*16 + grp;
        #pragma unroll
        for (int nt = 0; nt < 8; nt++) {
            int c0 = warp_n*64 + nt*8 + tig*2;
            #pragma unroll
            for (int q = 0; q < 4; q++) {
                int c = c0 + (q & 1);
                int r = (q < 2) ? rA : rA + 8;
                if (c >= OUTC) continue;
                float v = acc[nt][q] + sb3[c];
                if (c < 3)       out[O_CENTER + r*3 + c] = g_newxyz[r*3 + c] + v;
                else if (c < 5)  out[O_OBJ + r*2 + (c-3)] = v;
                else if (c < 17) out[O_HS + r*12 + (c-5)] = v;
                else if (c < 35) out[O_SS + r*18 + (c-17)] = v;
                else if (c < 47) { out[O_HRN + r*12 + (c-35)] = v; out[O_HR + r*12 + (c-35)] = v * HRS; }
                else if (c < 101){ int s = c - 47; out[O_SRN + r*54 + s] = v; out[O_SR + r*54 + s] = v * sms[s]; }
                else             out[O_SEM + r*18 + (c-101)] = v;
            }
        }
    }
}

// ---------------- launch ----------------
extern "C" void kernel_launch(void* const* d_in, const int* in_sizes, int n_in,
                              void* d_out, int out_size) {
    const float* xyz      = (const float*)d_in[0];
    const float* features = (const float*)d_in[1];
    const float* msz      = (const float*)d_in[2];
    const float* w0  = (const float*)d_in[3];
    const float* b0  = (const float*)d_in[4];
    const float* gm0 = (const float*)d_in[5];
    const float* be0 = (const float*)d_in[6];
    const float* wm1 = (const float*)d_in[7];
    const float* bm1 = (const float*)d_in[8];
    const float* gm1 = (const float*)d_in[9];
    const float* bem1= (const float*)d_in[10];
    const float* wm2 = (const float*)d_in[11];
    const float* bm2 = (const float*)d_in[12];
    const float* gm2 = (const float*)d_in[13];
    const float* bem2= (const float*)d_in[14];
    const float* w1  = (const float*)d_in[15];
    const float* b1  = (const float*)d_in[16];
    const float* g1  = (const float*)d_in[17];
    const float* be1 = (const float*)d_in[18];
    const float* w2  = (const float*)d_in[19];
    const float* b2  = (const float*)d_in[20];
    const float* g2  = (const float*)d_in[21];
    const float* be2 = (const float*)d_in[22];
    const float* w3  = (const float*)d_in[23];
    const float* b3  = (const float*)d_in[24];
    float* out = (float*)d_out;

    cudaFuncSetAttribute(fused_mlp_kernel, cudaFuncAttributeMaxDynamicSharedMemorySize, 167936);
    cudaFuncSetAttribute(fused_fc_kernel,  cudaFuncAttributeMaxDynamicSharedMemorySize, 131072);

    fps_prep_kernel<<<148, 128>>>(xyz, w0, wm1, wm2, w1, w2, w3, out);
    fused_mlp_kernel<<<NROWS/256, 512, 167936>>>(xyz, features,
                                                 b0, gm0, be0,
                                                 bm1, gm1, bem1,
                                                 bm2, gm2, bem2);
    fused_fc_kernel<<<NG/64, 256, 131072>>>(b1, g1, be1, b2, g2, be2, b3, msz, out);
}

// round 14
// speedup vs baseline: 1.5222x; 1.5222x over previous
#include <cuda_runtime.h>
#include <cuda_fp16.h>
#include <cstdint>

#define BB    32
#define KK    1024
#define CC    256
#define PP    256
#define NSAMP 16
#define NROWS (BB*PP*NSAMP)   // 131072
#define NG    (BB*PP)         // 8192
#define HID   128
#define OUTC  119

// output segment offsets (floats): obj, center, hs, hrn, hr, ss, srn, sr, sem, new_xyz, inds
#define O_OBJ    0
#define O_CENTER 16384
#define O_HS     40960
#define O_HRN    139264
#define O_HR     237568
#define O_SS     335872
#define O_SRN    483328
#define O_SR     925696
#define O_SEM    1368064
#define O_NEWXYZ 1515520
#define O_INDS   1540096

// ---------------- scratch ----------------
__device__ int   g_inds[NG];
__device__ float g_newxyz[NG*3];
__device__ int   g_idx[NROWS];
__device__ __align__(16) float g_feat[NG*HID];
// fp16 MLP weights in m16n8k16 B-fragment layout (word = uint32 = 2 halfs)
__device__ __align__(16) uint32_t g_w0h[17*16*32*2];  // K=272 (k 0..255=feats, 256..258=xyz, rest 0)
__device__ __align__(16) uint32_t g_w1h[8*16*32*2];
__device__ __align__(16) uint32_t g_w2h[8*16*32*2];
// tf32 FC weights, hi + lo residual, m16n8k8 B-fragment layout
__device__ __align__(16) float g_fw1f[16384], g_fl1f[16384];
__device__ __align__(16) float g_fw2f[16384], g_fl2f[16384];
__device__ __align__(16) float g_fw3f[16384], g_fl3f[16384];  // head, N padded 119->128

__device__ __forceinline__ float tf32r(float v) {
    float o;
    asm("cvt.rna.tf32.f32 %0, %1;" : "=f"(o) : "f"(v));
    return o;
}
__device__ __forceinline__ uint32_t packh2(float a, float b) {
    __half2 h = __floats2half2_rn(a, b);
    return *(uint32_t*)&h;
}
__device__ __forceinline__ uint32_t redux_max_u32(uint32_t v) {
    uint32_t r;
    asm volatile("redux.sync.max.u32 %0, %1, 0xffffffff;" : "=r"(r) : "r"(v));
    return r;
}
__device__ __forceinline__ uint32_t redux_min_u32(uint32_t v) {
    uint32_t r;
    asm volatile("redux.sync.min.u32 %0, %1, 0xffffffff;" : "=r"(r) : "r"(v));
    return r;
}

// fp16 mma m16n8k16
__device__ __forceinline__ void mma16(float c[4], uint32_t a0, uint32_t a1, uint32_t a2, uint32_t a3,
                                      uint32_t b0, uint32_t b1) {
    asm volatile(
        "mma.sync.aligned.m16n8k16.row.col.f32.f16.f16.f32 "
        "{%0,%1,%2,%3}, {%4,%5,%6,%7}, {%8,%9}, {%0,%1,%2,%3};\n"
        : "+f"(c[0]), "+f"(c[1]), "+f"(c[2]), "+f"(c[3])
        : "r"(a0), "r"(a1), "r"(a2), "r"(a3), "r"(b0), "r"(b1));
}
// tf32 mma m16n8k8
__device__ __forceinline__ void mma8(float c[4], const float a[4], float b0, float b1) {
    asm volatile(
        "mma.sync.aligned.m16n8k8.row.col.f32.tf32.tf32.f32 "
        "{%0,%1,%2,%3}, {%4,%5,%6,%7}, {%8,%9}, {%0,%1,%2,%3};\n"
        : "+f"(c[0]), "+f"(c[1]), "+f"(c[2]), "+f"(c[3])
        : "r"(__float_as_uint(a[0])), "r"(__float_as_uint(a[1])),
          "r"(__float_as_uint(a[2])), "r"(__float_as_uint(a[3])),
          "r"(__float_as_uint(b0)), "r"(__float_as_uint(b1)));
}

// tf32 B-fragment scatter (k8 tiles)
__device__ __forceinline__ void bfrag_store(float* dst, int k, int n, float v) {
    int kt = k >> 3, kin = k & 7, ntl = n >> 3, gq = n & 7;
    int lane = gq*4 + (kin & 3), slot = kin >> 2;
    dst[((kt*16 + ntl)*32 + lane)*2 + slot] = v;
}
// fp16 B-fragment scatter (k16 tiles); writes one half
__device__ __forceinline__ void bfrag16_store(uint32_t* dst, int k, int n, __half v) {
    int kt = k >> 4, kin = k & 15, ntl = n >> 3, gq = n & 7;
    int lane = gq*4 + ((kin >> 1) & 3), reg = kin >> 3;
    __half* p = (__half*)&dst[((kt*16 + ntl)*32 + lane)*2 + reg];
    p[k & 1] = v;
}

// fp16 A-fragment pair store
__device__ __forceinline__ void a16pair(uint32_t* frag_mbase, int grp, int rowhi, int kp, uint32_t packed) {
    frag_mbase[(grp*4 + (kp & 3))*4 + ((kp & 4) ? 2 : 0) + rowhi] = packed;
}

// ---------------- FPS (blocks 0..31: 2 warps, 16 pts/thread) + weight prep (32..147) ----------------
__global__ __launch_bounds__(128)
void fps_prep_kernel(const float* __restrict__ xyz,
                     const float* __restrict__ w0,
                     const float* __restrict__ wm1,
                     const float* __restrict__ wm2,
                     const float* __restrict__ w1,
                     const float* __restrict__ w2,
                     const float* __restrict__ w3,
                     float* __restrict__ out) {
    __shared__ float4 sp4[KK];
    __shared__ uint2  swc[2][2];   // [parity][warp] = (dist bits, global idx)
    __shared__ short  s_sel[PP];

    if (blockIdx.x >= 32) {
        // ---- weight prep: 116 blocks x 128 threads over 116736 elements ----
        for (int i = (blockIdx.x - 32) * 128 + threadIdx.x; i < 116736; i += 116 * 128) {
            if (i < 34816) {             // w0h: K permuted+padded to 272
                int kd = i >> 7, n = i & 127;
                float v = 0.0f;
                if (kd < 256)      v = w0[(size_t)(kd + 3)*128 + n];
                else if (kd < 259) v = w0[(size_t)(kd - 256)*128 + n];
                bfrag16_store(g_w0h, kd, n, __float2half_rn(v));
            } else if (i < 51200) {
                int j = i - 34816; int k = j >> 7, n = j & 127;
                bfrag16_store(g_w1h, k, n, __float2half_rn(wm1[j]));
            } else if (i < 67584) {
                int j = i - 51200; int k = j >> 7, n = j & 127;
                bfrag16_store(g_w2h, k, n, __float2half_rn(wm2[j]));
            } else if (i < 83968) {
                int j = i - 67584; int k = j >> 7, n = j & 127;
                float w = w1[j]; float hi = tf32r(w);
                bfrag_store(g_fw1f, k, n, hi);
                bfrag_store(g_fl1f, k, n, tf32r(w - hi));
            } else if (i < 100352) {
                int j = i - 83968; int k = j >> 7, n = j & 127;
                float w = w2[j]; float hi = tf32r(w);
                bfrag_store(g_fw2f, k, n, hi);
                bfrag_store(g_fl2f, k, n, tf32r(w - hi));
            } else {
                int j = i - 100352; int k = j >> 7, n = j & 127;
                float w = (n < OUTC) ? w3[(size_t)k*OUTC + n] : 0.0f;
                float hi = tf32r(w);
                bfrag_store(g_fw3f, k, n, hi);
                bfrag_store(g_fl3f, k, n, tf32r(w - hi));
            }
        }
        return;
    }

    const int b = blockIdx.x;
    const int t = threadIdx.x;      // 0..127
    const float* xb = xyz + (size_t)b * KK * 3;

    for (int i = t; i < KK; i += 128)
        sp4[i] = make_float4(xb[i*3+0], xb[i*3+1], xb[i*3+2], 0.0f);
    if (t == 0) s_sel[0] = 0;
    __syncthreads();
    if (t >= 64) return;            // FPS loop uses 2 warps only

    const int w = t >> 5, lane = t & 31;

    // this thread owns points t*16 .. t*16+15 (registers)
    float px[16], py[16], pz[16], dist[16];
    #pragma unroll
    for (int q = 0; q < 16; q++) {
        float4 p = sp4[t*16 + q];
        px[q] = p.x; py[q] = p.y; pz[q] = p.z;
        dist[q] = 1e10f;
    }
    float4 lp = sp4[0];

    for (int it = 1; it < PP; it++) {
        float best = -1.0f; int bidx = 0;
        #pragma unroll
        for (int q = 0; q < 16; q++) {
            float dx = px[q] - lp.x, dy = py[q] - lp.y, dz = pz[q] - lp.z;
            float d = fmaf(dz, dz, fmaf(dy, dy, dx*dx));
            d = fminf(dist[q], d);
            dist[q] = d;
            if (d > best) { best = d; bidx = t*16 + q; }   // strict > keeps first q
        }
        uint32_t mv = redux_max_u32(__float_as_uint(best));
        uint32_t cand = (__float_as_uint(best) == mv) ? (uint32_t)bidx : 0xFFFFFFFFu;
        uint32_t widx = redux_min_u32(cand);

        if (lane == 0) swc[it & 1][w] = make_uint2(mv, widx);
        __syncthreads();

        uint2 c0 = swc[it & 1][0];
        uint2 c1 = swc[it & 1][1];
        uint32_t bi = (c1.x > c0.x || (c1.x == c0.x && c1.y < c0.y)) ? c1.y : c0.y;
        lp = sp4[bi];
        if (t == 0) s_sel[it] = (short)bi;
    }
    __syncthreads();

    // final writes: inds + new_xyz (scratch + output)
    for (int e = t; e < PP; e += 64) {
        int ci = s_sel[e];
        g_inds[b*PP + e] = ci;
        out[O_INDS + b*PP + e] = (float)ci;
        float4 c = sp4[ci];
        int base = (b*PP + e)*3;
        g_newxyz[base+0] = c.x; g_newxyz[base+1] = c.y; g_newxyz[base+2] = c.z;
        out[O_NEWXYZ + base + 0] = c.x;
        out[O_NEWXYZ + base + 1] = c.y;
        out[O_NEWXYZ + base + 2] = c.z;
    }
}

// ---------------- ball query (separate launch, wide parallelism) ----------------
__global__ void bq_kernel(const float* __restrict__ xyz) {
    __shared__ float4 sp4[KK];
    const int b = blockIdx.x;
    const int t = threadIdx.x;   // 1024
    const float* xb = xyz + (size_t)b * KK * 3;
    sp4[t] = make_float4(xb[t*3+0], xb[t*3+1], xb[t*3+2], 0.0f);
    __syncthreads();
    if (t >= PP) return;

    float4 qp = sp4[g_inds[b*PP + t]];
    int buf[NSAMP]; int cnt = 0;
    #pragma unroll 4
    for (int j = 0; j < KK; j++) {
        float4 p = sp4[j];
        float dx = qp.x - p.x, dy = qp.y - p.y, dz = qp.z - p.z;
        float d = fmaf(dz, dz, fmaf(dy, dy, dx*dx));
        if (d < 0.09f) { if (cnt < NSAMP) buf[cnt] = j; cnt++; }
    }
    if (cnt == 0) { for (int s = 0; s < NSAMP; s++) buf[s] = KK - 1; }
    else { int c = cnt < NSAMP ? cnt : NSAMP; for (int s = c; s < NSAMP; s++) buf[s] = buf[0]; }
    const int gp = b*PP + t;
    #pragma unroll
    for (int s = 0; s < NSAMP; s++) g_idx[gp*NSAMP + s] = buf[s];
}

// ---------------- fused layer0+1+2+maxpool (fp16 mma, M=256, 512 threads) ----------------
// smem word map (uint32, total 41984 words = 164KB):
//   B0  [0, 17408)        — dead after L0; A_L1 overlays [0, 16384)
//   B2  [17408, 25600)
//   B1  [25600, 33792)    — dead after L1; A_L2 overlays [25600, 41984) (also covers Ach)
//   Ach [33792, 41984)    — gather ring, 4 x 2048 words, dead after L0
__global__ __launch_bounds__(512, 1)
void fused_mlp_kernel(const float* __restrict__ xyz,
                      const float* __restrict__ feats,
                      const float* __restrict__ b0, const float* __restrict__ g0, const float* __restrict__ e0,
                      const float* __restrict__ b1, const float* __restrict__ g1, const float* __restrict__ e1,
                      const float* __restrict__ b2, const float* __restrict__ g2, const float* __restrict__ e2) {
    extern __shared__ uint32_t smw[];
    __shared__ float sg[3][128], sb[3][128], se[3][128];
    __shared__ int   sj[256];
    __shared__ float sg3s[256][3];

    const int tid = threadIdx.x, lane = tid & 31, wid = tid >> 5;
    const int warp_m = wid >> 1, warp_n = wid & 1;   // warp_m 0..7
    const int grp = lane >> 2, tig = lane & 3;
    const int tile = blockIdx.x, row0 = tile * 256;

    if (tid < 128) {
        sg[0][tid] = g0[tid]; sb[0][tid] = b0[tid]; se[0][tid] = e0[tid];
        sg[1][tid] = g1[tid]; sb[1][tid] = b1[tid]; se[1][tid] = e1[tid];
        sg[2][tid] = g2[tid]; sb[2][tid] = b2[tid]; se[2][tid] = e2[tid];
    }
    if (tid < 256) {
        int grow = row0 + tid;
        int bb = grow >> 12;
        int p = (grow & 4095) >> 4;
        int j = g_idx[grow];
        sj[tid] = j;
        int gp = bb * PP + p;
        #pragma unroll
        for (int d = 0; d < 3; d++)
            sg3s[tid][d] = __fdiv_rn(xyz[(size_t)(bb*KK + j)*3 + d] - g_newxyz[gp*3 + d], 0.3f);
    }
    __syncthreads();   // sj ready

    // stage all B (fp16): B0 4352 uint4, B2/B1 2048 each
    {
        const uint4* s0 = (const uint4*)g_w0h;
        uint4* d0 = (uint4*)smw;
        for (int q = tid; q < 4352; q += 512) d0[q] = s0[q];
        const uint4* s2 = (const uint4*)g_w2h;
        uint4* d2 = (uint4*)(smw + 17408);
        for (int q = tid; q < 2048; q += 512) d2[q] = s2[q];
        const uint4* s1 = (const uint4*)g_w1h;
        uint4* d1 = (uint4*)(smw + 25600);
        for (int q = tid; q < 2048; q += 512) d1[q] = s1[q];
    }

    const int ar = tid >> 1, h = tid & 1;   // ar 0..255
    const float4* frow4 = (const float4*)(feats + (size_t)((row0 >> 12) * KK + sj[ar]) * CC);
    const int m_tile_f = ar >> 4;           // 0..15
    const int R = ar & 15;
    const int grpa = R & 7;
    const int rowhi = R >> 3;

    // prefill gather ring slots 0 and 1 (tiles 0 and 1, feature tiles)
    {
        uint32_t* Am0 = smw + 33792 + 0*2048 + m_tile_f*128;
        float4 a0 = frow4[h*2], a1 = frow4[h*2 + 1];
        a16pair(Am0, grpa, rowhi, h*4+0, packh2(a0.x, a0.y));
        a16pair(Am0, grpa, rowhi, h*4+1, packh2(a0.z, a0.w));
        a16pair(Am0, grpa, rowhi, h*4+2, packh2(a1.x, a1.y));
        a16pair(Am0, grpa, rowhi, h*4+3, packh2(a1.z, a1.w));
        uint32_t* Am1 = smw + 33792 + 1*2048 + m_tile_f*128;
        float4 b0v = frow4[4 + h*2], b1v = frow4[4 + h*2 + 1];
        a16pair(Am1, grpa, rowhi, h*4+0, packh2(b0v.x, b0v.y));
        a16pair(Am1, grpa, rowhi, h*4+1, packh2(b0v.z, b0v.w));
        a16pair(Am1, grpa, rowhi, h*4+2, packh2(b1v.x, b1v.y));
        a16pair(Am1, grpa, rowhi, h*4+3, packh2(b1v.z, b1v.w));
    }
    __syncthreads();

    float acc[2][8][4];
    #pragma unroll
    for (int mt = 0; mt < 2; mt++)
        #pragma unroll
        for (int nt = 0; nt < 8; nt++)
            #pragma unroll
            for (int q = 0; q < 4; q++) acc[mt][nt][q] = 0.0f;

    // ---- layer 0: 17 k16-tiles, 4-slot ring, prefetch distance 2, sync every 2 tiles ----
    for (int kt = 0; kt < 17; kt++) {
        const int ft = kt + 2;               // tile to fill this iteration
        float4 n0, n1;
        if (ft <= 15) { n0 = frow4[ft*4 + h*2]; n1 = frow4[ft*4 + h*2 + 1]; }

        const uint32_t* Ac = smw + 33792 + (kt & 3)*2048;
        #pragma unroll
        for (int mt = 0; mt < 2; mt++) {
            uint4 av = *(const uint4*)&Ac[(warp_m*2 + mt)*128 + lane*4];
            #pragma unroll
            for (int nt = 0; nt < 8; nt++) {
                uint2 bv = *(const uint2*)&smw[kt*1024 + (warp_n*8 + nt)*64 + lane*2];
                mma16(acc[mt][nt], av.x, av.y, av.z, av.w, bv.x, bv.y);
            }
        }

        if (ft <= 16) {
            uint32_t* Am = smw + 33792 + (ft & 3)*2048 + m_tile_f*128;
            if (ft <= 15) {
                a16pair(Am, grpa, rowhi, h*4+0, packh2(n0.x, n0.y));
                a16pair(Am, grpa, rowhi, h*4+1, packh2(n0.z, n0.w));
                a16pair(Am, grpa, rowhi, h*4+2, packh2(n1.x, n1.y));
                a16pair(Am, grpa, rowhi, h*4+3, packh2(n1.z, n1.w));
            } else {                          // ft == 16: xyz chunk
                uint32_t p0 = 0, p1 = 0;
                if (h == 0) {
                    p0 = packh2(sg3s[ar][0], sg3s[ar][1]);
                    p1 = packh2(sg3s[ar][2], 0.0f);
                }
                a16pair(Am, grpa, rowhi, h*4+0, p0);
                a16pair(Am, grpa, rowhi, h*4+1, p1);
                a16pair(Am, grpa, rowhi, h*4+2, 0u);
                a16pair(Am, grpa, rowhi, h*4+3, 0u);
            }
        }
        if (kt & 1) __syncthreads();
    }
    __syncthreads();   // all reads of B0 + Ach done before overlays

    // epilogue helper: next layer's fp16 A-frag into dstw, zero acc
    auto epi16 = [&](uint32_t* dstw, int li) {
        #pragma unroll
        for (int mt = 0; mt < 2; mt++) {
            #pragma unroll
            for (int nt = 0; nt < 8; nt++) {
                int c = warp_n*64 + nt*8 + tig*2;
                float ga = sg[li][c], gb = sg[li][c+1];
                float ba = sb[li][c], bbv = sb[li][c+1];
                float ea = se[li][c], eb = se[li][c+1];
                float v0 = fmaxf(fmaf(ga, acc[mt][nt][0] + ba, ea), 0.0f);
                float v1 = fmaxf(fmaf(gb, acc[mt][nt][1] + bbv, eb), 0.0f);
                float v2 = fmaxf(fmaf(ga, acc[mt][nt][2] + ba, ea), 0.0f);
                float v3 = fmaxf(fmaf(gb, acc[mt][nt][3] + bbv, eb), 0.0f);
                int k_tile = warp_n*4 + (nt >> 1);
                uint32_t* p = dstw + ((warp_m*2 + mt)*8 + k_tile)*128 + (grp*4 + tig)*4 + (nt & 1)*2;
                *(uint2*)p = make_uint2(packh2(v0, v1), packh2(v2, v3));
                acc[mt][nt][0] = 0.f; acc[mt][nt][1] = 0.f; acc[mt][nt][2] = 0.f; acc[mt][nt][3] = 0.f;
            }
        }
    };

    epi16(smw, 0);            // A_L1 over B0 region [0,16384)
    __syncthreads();

    // ---- layer 1: A_L1 @ smw, B1 @ smw+25600 ----
    #pragma unroll
    for (int ks = 0; ks < 8; ks++) {
        #pragma unroll
        for (int mt = 0; mt < 2; mt++) {
            uint4 av = *(const uint4*)&smw[((warp_m*2 + mt)*8 + ks)*128 + lane*4];
            #pragma unroll
            for (int nt = 0; nt < 8; nt++) {
                uint2 bv = *(const uint2*)&smw[25600 + ks*1024 + (warp_n*8 + nt)*64 + lane*2];
                mma16(acc[mt][nt], av.x, av.y, av.z, av.w, bv.x, bv.y);
            }
        }
    }
    __syncthreads();          // all warps done reading B1/A_L1
    epi16(smw + 25600, 1);    // A_L2 over B1+Ach [25600,41984)
    __syncthreads();

    // ---- layer 2: A_L2 @ smw+25600, B2 @ smw+17408 ----
    #pragma unroll
    for (int ks = 0; ks < 8; ks++) {
        #pragma unroll
        for (int mt = 0; mt < 2; mt++) {
            uint4 av = *(const uint4*)&smw[25600 + ((warp_m*2 + mt)*8 + ks)*128 + lane*4];
            #pragma unroll
            for (int nt = 0; nt < 8; nt++) {
                uint2 bv = *(const uint2*)&smw[17408 + ks*1024 + (warp_n*8 + nt)*64 + lane*2];
                mma16(acc[mt][nt], av.x, av.y, av.z, av.w, bv.x, bv.y);
            }
        }
    }

    // ---- maxpool epilogue (16 groups of 16 rows) ----
    #pragma unroll
    for (int mt = 0; mt < 2; mt++) {
        int gidx = tile*16 + warp_m*2 + mt;
        #pragma unroll
        for (int nt = 0; nt < 8; nt++) {
            int c = warp_n*64 + nt*8 + tig*2;
            float ga = sg[2][c], gb = sg[2][c+1];
            float ba = sb[2][c], bbv = sb[2][c+1];
            float ea = se[2][c], eb = se[2][c+1];
            float v0 = fmaxf(fmaf(ga, acc[mt][nt][0] + ba, ea), 0.0f);
            float v1 = fmaxf(fmaf(gb, acc[mt][nt][1] + bbv, eb), 0.0f);
            float v2 = fmaxf(fmaf(ga, acc[mt][nt][2] + ba, ea), 0.0f);
            float v3 = fmaxf(fmaf(gb, acc[mt][nt][3] + bbv, eb), 0.0f);
            float mA = fmaxf(v0, v2), mB = fmaxf(v1, v3);
            #pragma unroll
            for (int o = 4; o < 32; o <<= 1) {
                mA = fmaxf(mA, __shfl_xor_sync(0xffffffffu, mA, o));
                mB = fmaxf(mB, __shfl_xor_sync(0xffffffffu, mB, o));
            }
            if (grp == 0) {
                g_feat[(size_t)gidx*128 + c]     = mA;
                g_feat[(size_t)gidx*128 + c + 1] = mB;
            }
        }
    }
}

// ---------------- FC helpers (tf32 path) ----------------
__device__ __forceinline__ void afrag_sts4_fc(float* A, int m_tile, int kl0,
                                              int laneRow, int slotR, float4 v) {
    int ktl = kl0 >> 3;
    int kin0 = kl0 & 7;
    int base = (m_tile*16 + ktl)*128 + laneRow*16 + slotR + ((kin0 < 4) ? 0 : 2);
    A[base + 0]  = tf32r(v.x);
    A[base + 4]  = tf32r(v.y);
    A[base + 8]  = tf32r(v.z);
    A[base + 12] = tf32r(v.w);
}

// M=64 tile GEMM: each warp owns m_tile = warp_m (0..3), N-half = warp_n
__device__ __forceinline__ void mma_64(const float* Af, const float* Bst,
                                       float acc[8][4],
                                       int warp_m, int warp_n, int lane) {
    #pragma unroll
    for (int ks = 0; ks < 16; ks++) {
        float4 a0 = *(const float4*)&Af[(warp_m*16 + ks)*128 + lane*4];
        float2 bv[8];
        #pragma unroll
        for (int nt = 0; nt < 8; nt++)
            bv[nt] = *(const float2*)&Bst[((ks*16 + warp_n*8 + nt)*32 + lane)*2];
        #pragma unroll
        for (int nt = 0; nt < 8; nt++)
            mma8(acc[nt], (const float*)&a0, bv[nt].x, bv[nt].y);
    }
}

// ---------------- fused FC1+FC2+head, error-compensated tf32 (M=64, grid=128) ----------------
// smem floats: A_hi [0,8192), A_lo [8192,16384), Bst [16384,32768)  (128KB)
__global__ __launch_bounds__(256)
void fused_fc_kernel(const float* __restrict__ b1, const float* __restrict__ g1, const float* __restrict__ e1,
                     const float* __restrict__ b2, const float* __restrict__ g2, const float* __restrict__ e2,
                     const float* __restrict__ b3, const float* __restrict__ msz,
                     float* __restrict__ out) {
    extern __shared__ float sm[];
    float* A_hi = sm;
    float* A_lo = sm + 8192;
    float* Bst  = sm + 16384;
    __shared__ float sg1[128], sb1[128], se1[128], sg2[128], sb2[128], se2[128];
    __shared__ float sb3[128], sms[54];

    const int tid = threadIdx.x, lane = tid & 31, wid = tid >> 5;
    const int warp_m = wid >> 1, warp_n = wid & 1;   // warp_m 0..3 = m_tile
    const int grp = lane >> 2, tig = lane & 3;
    const int row0 = blockIdx.x * 64;

    if (tid < 128) {
        sg1[tid] = g1[tid]; sb1[tid] = b1[tid]; se1[tid] = e1[tid];
        sg2[tid] = g2[tid]; sb2[tid] = b2[tid]; se2[tid] = e2[tid];
        sb3[tid] = (tid < OUTC) ? b3[tid] : 0.0f;
    } else if (tid < 182) {
        sms[tid - 128] = msz[tid - 128];
    }

    // fill A_hi / A_lo from g_feat: 64 rows, 4 threads/row (32 cols each)
    const int ar = tid >> 2, h = tid & 3;
    const int m_tile_f = ar >> 4;
    const int R = ar & 15;
    const int laneRow = R & 7;
    const int slotR = (R < 8) ? 0 : 1;
    {
        const float4* frow4 = (const float4*)(g_feat + (size_t)(row0 + ar) * 128);
        #pragma unroll
        for (int j = 0; j < 8; j++) {
            float4 v = frow4[h*8 + j];
            float4 hi = make_float4(tf32r(v.x), tf32r(v.y), tf32r(v.z), tf32r(v.w));
            float4 lo = make_float4(v.x - hi.x, v.y - hi.y, v.z - hi.z, v.w - hi.w);
            afrag_sts4_fc(A_hi, m_tile_f, h*32 + j*4, laneRow, slotR, hi);
            afrag_sts4_fc(A_lo, m_tile_f, h*32 + j*4, laneRow, slotR, lo);
        }
    }

    float acc[8][4];
    #pragma unroll
    for (int nt = 0; nt < 8; nt++)
        #pragma unroll
        for (int q = 0; q < 4; q++) acc[nt][q] = 0.0f;

    auto stage = [&](const float* src) {
        const float4* s = (const float4*)src;
        float4* d = (float4*)Bst;
        #pragma unroll
        for (int q = 0; q < 16; q++) d[tid + q*256] = s[tid + q*256];
    };
    // compensated epilogue: relu6 affine -> hi/lo in place
    auto epi_hilo = [&](const float* sgp, const float* sbp, const float* sep) {
        const int la0 = grp*4 + ((2*tig) & 3);
        const int slot_hi = (tig < 2) ? 0 : 2;
        #pragma unroll
        for (int nt = 0; nt < 8; nt++) {
            int c = warp_n*64 + nt*8 + tig*2;
            float ga = sgp[c], gb = sgp[c+1], ba = sbp[c], bbv = sbp[c+1], ea = sep[c], eb = sep[c+1];
            float v0 = fminf(fmaxf(fmaf(ga, acc[nt][0] + ba, ea), 0.0f), 6.0f);
            float v1 = fminf(fmaxf(fmaf(gb, acc[nt][1] + bbv, eb), 0.0f), 6.0f);
            float v2 = fminf(fmaxf(fmaf(ga, acc[nt][2] + ba, ea), 0.0f), 6.0f);
            float v3 = fminf(fmaxf(fmaf(gb, acc[nt][3] + bbv, eb), 0.0f), 6.0f);
            float h0 = tf32r(v0), h1 = tf32r(v1), h2 = tf32r(v2), h3 = tf32r(v3);
            int kt = warp_n*8 + nt;
            float* pH = A_hi + (warp_m*16 + kt)*128 + la0*4 + slot_hi;
            float* pL = A_lo + (warp_m*16 + kt)*128 + la0*4 + slot_hi;
            *(float2*)pH       = make_float2(h0, h2);
            *(float2*)(pH + 4) = make_float2(h1, h3);
            *(float2*)pL       = make_float2(tf32r(v0 - h0), tf32r(v2 - h2));
            *(float2*)(pL + 4) = make_float2(tf32r(v1 - h1), tf32r(v3 - h3));
            acc[nt][0] = 0.f; acc[nt][1] = 0.f; acc[nt][2] = 0.f; acc[nt][3] = 0.f;
        }
    };

    // ---- FC1 ----
    stage(g_fw1f);
    __syncthreads();
    mma_64(A_hi, Bst, acc, warp_m, warp_n, lane);
    mma_64(A_lo, Bst, acc, warp_m, warp_n, lane);
    __syncthreads();
    stage(g_fl1f);
    __syncthreads();
    mma_64(A_hi, Bst, acc, warp_m, warp_n, lane);
    __syncthreads();
    epi_hilo(sg1, sb1, se1);
    __syncthreads();

    // ---- FC2 ----
    stage(g_fw2f);
    __syncthreads();
    mma_64(A_hi, Bst, acc, warp_m, warp_n, lane);
    mma_64(A_lo, Bst, acc, warp_m, warp_n, lane);
    __syncthreads();
    stage(g_fl2f);
    __syncthreads();
    mma_64(A_hi, Bst, acc, warp_m, warp_n, lane);
    __syncthreads();
    epi_hilo(sg2, sb2, se2);
    __syncthreads();

    // ---- head ----
    stage(g_fw3f);
    __syncthreads();
    mma_64(A_hi, Bst, acc, warp_m, warp_n, lane);
    mma_64(A_lo, Bst, acc, warp_m, warp_n, lane);
    __syncthreads();
    stage(g_fl3f);
    __syncthreads();
    mma_64(A_hi, Bst, acc, warp_m, warp_n, lane);

    // head scatter from accumulator frags
    const float HRS = (float)(3.14159265359 / 12.0);
    {
        int rA = row0 + warp_m*16 + grp;
        #pragma unroll
        for (int nt = 0; nt < 8; nt++) {
            int c0 = warp_n*64 + nt*8 + tig*2;
            #pragma unroll
            for (int q = 0; q < 4; q++) {
                int c = c0 + (q & 1);
                int r = (q < 2) ? rA : rA + 8;
                if (c >= OUTC) continue;
                float v = acc[nt][q] + sb3[c];
                if (c < 3)       out[O_CENTER + r*3 + c] = g_newxyz[r*3 + c] + v;
                else if (c < 5)  out[O_OBJ + r*2 + (c-3)] = v;
                else if (c < 17) out[O_HS + r*12 + (c-5)] = v;
                else if (c < 35) out[O_SS + r*18 + (c-17)] = v;
                else if (c < 47) { out[O_HRN + r*12 + (c-35)] = v; out[O_HR + r*12 + (c-35)] = v * HRS; }
                else if (c < 101){ int s = c - 47; out[O_SRN + r*54 + s] = v; out[O_SR + r*54 + s] = v * sms[s]; }
                else             out[O_SEM + r*18 + (c-101)] = v;
            }
        }
    }
}

// ---------------- launch ----------------
extern "C" void kernel_launch(void* const* d_in, const int* in_sizes, int n_in,
                              void* d_out, int out_size) {
    const float* xyz      = (const float*)d_in[0];
    const float* features = (const float*)d_in[1];
    const float* msz      = (const float*)d_in[2];
    const float* w0  = (const float*)d_in[3];
    const float* b0  = (const float*)d_in[4];
    const float* gm0 = (const float*)d_in[5];
    const float* be0 = (const float*)d_in[6];
    const float* wm1 = (const float*)d_in[7];
    const float* bm1 = (const float*)d_in[8];
    const float* gm1 = (const float*)d_in[9];
    const float* bem1= (const float*)d_in[10];
    const float* wm2 = (const float*)d_in[11];
    const float* bm2 = (const float*)d_in[12];
    const float* gm2 = (const float*)d_in[13];
    const float* bem2= (const float*)d_in[14];
    const float* w1  = (const float*)d_in[15];
    const float* b1  = (const float*)d_in[16];
    const float* g1  = (const float*)d_in[17];
    const float* be1 = (const float*)d_in[18];
    const float* w2  = (const float*)d_in[19];
    const float* b2  = (const float*)d_in[20];
    const float* g2  = (const float*)d_in[21];
    const float* be2 = (const float*)d_in[22];
    const float* w3  = (const float*)d_in[23];
    const float* b3  = (const float*)d_in[24];
    float* out = (float*)d_out;

    cudaFuncSetAttribute(fused_mlp_kernel, cudaFuncAttributeMaxDynamicSharedMemorySize, 167936);
    cudaFuncSetAttribute(fused_fc_kernel,  cudaFuncAttributeMaxDynamicSharedMemorySize, 131072);

    fps_prep_kernel<<<148, 128>>>(xyz, w0, wm1, wm2, w1, w2, w3, out);
    bq_kernel<<<BB, 1024>>>(xyz);
    fused_mlp_kernel<<<NROWS/256, 512, 167936>>>(xyz, features,
                                                 b0, gm0, be0,
                                                 bm1, gm1, bem1,
                                                 bm2, gm2, bem2);
    fused_fc_kernel<<<NG/64, 256, 131072>>>(b1, g1, be1, b2, g2, be2, b3, msz, out);
}

// round 15
// speedup vs baseline: 1.5848x; 1.0411x over previous
#include <cuda_runtime.h>
#include <cuda_fp16.h>
#include <cstdint>

#define BB    32
#define KK    1024
#define CC    256
#define PP    256
#define NSAMP 16
#define NROWS (BB*PP*NSAMP)   // 131072
#define NG    (BB*PP)         // 8192
#define HID   128
#define OUTC  119

// output segment offsets (floats): obj, center, hs, hrn, hr, ss, srn, sr, sem, new_xyz, inds
#define O_OBJ    0
#define O_CENTER 16384
#define O_HS     40960
#define O_HRN    139264
#define O_HR     237568
#define O_SS     335872
#define O_SRN    483328
#define O_SR     925696
#define O_SEM    1368064
#define O_NEWXYZ 1515520
#define O_INDS   1540096

// ---------------- scratch ----------------
__device__ int   g_inds[NG];
__device__ float g_newxyz[NG*3];
__device__ int   g_idx[NROWS];
__device__ __align__(16) float g_feat[NG*HID];
// fp16 MLP weights in m16n8k16 B-fragment layout (word = uint32 = 2 halfs)
__device__ __align__(16) uint32_t g_w0h[17*16*32*2];  // K=272 (k 0..255=feats, 256..258=xyz, rest 0)
__device__ __align__(16) uint32_t g_w1h[8*16*32*2];
__device__ __align__(16) uint32_t g_w2h[8*16*32*2];
// tf32 FC weights, hi + lo residual, m16n8k8 B-fragment layout
__device__ __align__(16) float g_fw1f[16384], g_fl1f[16384];
__device__ __align__(16) float g_fw2f[16384], g_fl2f[16384];
__device__ __align__(16) float g_fw3f[16384], g_fl3f[16384];  // head, N padded 119->128

__device__ __forceinline__ float tf32r(float v) {
    float o;
    asm("cvt.rna.tf32.f32 %0, %1;" : "=f"(o) : "f"(v));
    return o;
}
__device__ __forceinline__ uint32_t packh2(float a, float b) {
    __half2 h = __floats2half2_rn(a, b);
    return *(uint32_t*)&h;
}
__device__ __forceinline__ uint32_t redux_max_u32(uint32_t v) {
    uint32_t r;
    asm volatile("redux.sync.max.u32 %0, %1, 0xffffffff;" : "=r"(r) : "r"(v));
    return r;
}
__device__ __forceinline__ uint32_t redux_min_u32(uint32_t v) {
    uint32_t r;
    asm volatile("redux.sync.min.u32 %0, %1, 0xffffffff;" : "=r"(r) : "r"(v));
    return r;
}

// fp16 mma m16n8k16
__device__ __forceinline__ void mma16(float c[4], uint32_t a0, uint32_t a1, uint32_t a2, uint32_t a3,
                                      uint32_t b0, uint32_t b1) {
    asm volatile(
        "mma.sync.aligned.m16n8k16.row.col.f32.f16.f16.f32 "
        "{%0,%1,%2,%3}, {%4,%5,%6,%7}, {%8,%9}, {%0,%1,%2,%3};\n"
        : "+f"(c[0]), "+f"(c[1]), "+f"(c[2]), "+f"(c[3])
        : "r"(a0), "r"(a1), "r"(a2), "r"(a3), "r"(b0), "r"(b1));
}
// tf32 mma m16n8k8
__device__ __forceinline__ void mma8(float c[4], const float a[4], float b0, float b1) {
    asm volatile(
        "mma.sync.aligned.m16n8k8.row.col.f32.tf32.tf32.f32 "
        "{%0,%1,%2,%3}, {%4,%5,%6,%7}, {%8,%9}, {%0,%1,%2,%3};\n"
        : "+f"(c[0]), "+f"(c[1]), "+f"(c[2]), "+f"(c[3])
        : "r"(__float_as_uint(a[0])), "r"(__float_as_uint(a[1])),
          "r"(__float_as_uint(a[2])), "r"(__float_as_uint(a[3])),
          "r"(__float_as_uint(b0)), "r"(__float_as_uint(b1)));
}

// tf32 B-fragment scatter (k8 tiles)
__device__ __forceinline__ void bfrag_store(float* dst, int k, int n, float v) {
    int kt = k >> 3, kin = k & 7, ntl = n >> 3, gq = n & 7;
    int lane = gq*4 + (kin & 3), slot = kin >> 2;
    dst[((kt*16 + ntl)*32 + lane)*2 + slot] = v;
}
// fp16 B-fragment scatter (k16 tiles); writes one half
__device__ __forceinline__ void bfrag16_store(uint32_t* dst, int k, int n, __half v) {
    int kt = k >> 4, kin = k & 15, ntl = n >> 3, gq = n & 7;
    int lane = gq*4 + ((kin >> 1) & 3), reg = kin >> 3;
    __half* p = (__half*)&dst[((kt*16 + ntl)*32 + lane)*2 + reg];
    p[k & 1] = v;
}

// fp16 A-fragment pair store
__device__ __forceinline__ void a16pair(uint32_t* frag_mbase, int grp, int rowhi, int kp, uint32_t packed) {
    frag_mbase[(grp*4 + (kp & 3))*4 + ((kp & 4) ? 2 : 0) + rowhi] = packed;
}

// ---------------- FPS (blocks 0..31: 2 warps, 16 pts/thread) + weight prep (32..147) ----------------
__global__ __launch_bounds__(128)
void fps_prep_kernel(const float* __restrict__ xyz,
                     const float* __restrict__ w0,
                     const float* __restrict__ wm1,
                     const float* __restrict__ wm2,
                     const float* __restrict__ w1,
                     const float* __restrict__ w2,
                     const float* __restrict__ w3,
                     float* __restrict__ out) {
    __shared__ float4 sp4[KK];
    __shared__ uint2  swc[2][2];
    __shared__ short  s_sel[PP];

    if (blockIdx.x >= 32) {
        for (int i = (blockIdx.x - 32) * 128 + threadIdx.x; i < 116736; i += 116 * 128) {
            if (i < 34816) {             // w0h: K permuted+padded to 272
                int kd = i >> 7, n = i & 127;
                float v = 0.0f;
                if (kd < 256)      v = w0[(size_t)(kd + 3)*128 + n];
                else if (kd < 259) v = w0[(size_t)(kd - 256)*128 + n];
                bfrag16_store(g_w0h, kd, n, __float2half_rn(v));
            } else if (i < 51200) {
                int j = i - 34816; int k = j >> 7, n = j & 127;
                bfrag16_store(g_w1h, k, n, __float2half_rn(wm1[j]));
            } else if (i < 67584) {
                int j = i - 51200; int k = j >> 7, n = j & 127;
                bfrag16_store(g_w2h, k, n, __float2half_rn(wm2[j]));
            } else if (i < 83968) {
                int j = i - 67584; int k = j >> 7, n = j & 127;
                float w = w1[j]; float hi = tf32r(w);
                bfrag_store(g_fw1f, k, n, hi);
                bfrag_store(g_fl1f, k, n, tf32r(w - hi));
            } else if (i < 100352) {
                int j = i - 83968; int k = j >> 7, n = j & 127;
                float w = w2[j]; float hi = tf32r(w);
                bfrag_store(g_fw2f, k, n, hi);
                bfrag_store(g_fl2f, k, n, tf32r(w - hi));
            } else {
                int j = i - 100352; int k = j >> 7, n = j & 127;
                float w = (n < OUTC) ? w3[(size_t)k*OUTC + n] : 0.0f;
                float hi = tf32r(w);
                bfrag_store(g_fw3f, k, n, hi);
                bfrag_store(g_fl3f, k, n, tf32r(w - hi));
            }
        }
        return;
    }

    const int b = blockIdx.x;
    const int t = threadIdx.x;
    const float* xb = xyz + (size_t)b * KK * 3;

    for (int i = t; i < KK; i += 128)
        sp4[i] = make_float4(xb[i*3+0], xb[i*3+1], xb[i*3+2], 0.0f);
    if (t == 0) s_sel[0] = 0;
    __syncthreads();
    if (t >= 64) return;

    const int w = t >> 5, lane = t & 31;

    float px[16], py[16], pz[16], dist[16];
    #pragma unroll
    for (int q = 0; q < 16; q++) {
        float4 p = sp4[t*16 + q];
        px[q] = p.x; py[q] = p.y; pz[q] = p.z;
        dist[q] = 1e10f;
    }
    float4 lp = sp4[0];

    for (int it = 1; it < PP; it++) {
        float best = -1.0f; int bidx = 0;
        #pragma unroll
        for (int q = 0; q < 16; q++) {
            float dx = px[q] - lp.x, dy = py[q] - lp.y, dz = pz[q] - lp.z;
            float d = fmaf(dz, dz, fmaf(dy, dy, dx*dx));
            d = fminf(dist[q], d);
            dist[q] = d;
            if (d > best) { best = d; bidx = t*16 + q; }
        }
        uint32_t mv = redux_max_u32(__float_as_uint(best));
        uint32_t cand = (__float_as_uint(best) == mv) ? (uint32_t)bidx : 0xFFFFFFFFu;
        uint32_t widx = redux_min_u32(cand);

        if (lane == 0) swc[it & 1][w] = make_uint2(mv, widx);
        __syncthreads();

        uint2 c0 = swc[it & 1][0];
        uint2 c1 = swc[it & 1][1];
        uint32_t bi = (c1.x > c0.x || (c1.x == c0.x && c1.y < c0.y)) ? c1.y : c0.y;
        lp = sp4[bi];
        if (t == 0) s_sel[it] = (short)bi;
    }
    __syncthreads();

    for (int e = t; e < PP; e += 64) {
        int ci = s_sel[e];
        g_inds[b*PP + e] = ci;
        out[O_INDS + b*PP + e] = (float)ci;
        float4 c = sp4[ci];
        int base = (b*PP + e)*3;
        g_newxyz[base+0] = c.x; g_newxyz[base+1] = c.y; g_newxyz[base+2] = c.z;
        out[O_NEWXYZ + base + 0] = c.x;
        out[O_NEWXYZ + base + 1] = c.y;
        out[O_NEWXYZ + base + 2] = c.z;
    }
}

// ---------------- ball query (separate launch, wide parallelism) ----------------
__global__ void bq_kernel(const float* __restrict__ xyz) {
    __shared__ float4 sp4[KK];
    const int b = blockIdx.x;
    const int t = threadIdx.x;   // 1024
    const float* xb = xyz + (size_t)b * KK * 3;
    sp4[t] = make_float4(xb[t*3+0], xb[t*3+1], xb[t*3+2], 0.0f);
    __syncthreads();
    if (t >= PP) return;

    float4 qp = sp4[g_inds[b*PP + t]];
    int buf[NSAMP]; int cnt = 0;
    #pragma unroll 4
    for (int j = 0; j < KK; j++) {
        float4 p = sp4[j];
        float dx = qp.x - p.x, dy = qp.y - p.y, dz = qp.z - p.z;
        float d = fmaf(dz, dz, fmaf(dy, dy, dx*dx));
        if (d < 0.09f) { if (cnt < NSAMP) buf[cnt] = j; cnt++; }
    }
    if (cnt == 0) { for (int s = 0; s < NSAMP; s++) buf[s] = KK - 1; }
    else { int c = cnt < NSAMP ? cnt : NSAMP; for (int s = c; s < NSAMP; s++) buf[s] = buf[0]; }
    const int gp = b*PP + t;
    #pragma unroll
    for (int s = 0; s < NSAMP; s++) g_idx[gp*NSAMP + s] = buf[s];
}

// ---------------- fused layer0+1+2+maxpool (fp16 mma, M=128, 256 threads, 2 CTA/SM) ----------------
// smem word map (uint32, total 24576 words = 96KB):
//   R1 [0, 8192):  L0 phase: B0 ring 2x1024 @[0,2048), Ach ring 2x1024 @[2048,4096)
//                  after L0: A_L1 (8192 words)
//   R2 [8192, 16384): B1; after L1: A_L2
//   R3 [16384, 24576): B2
__global__ __launch_bounds__(256, 2)
void fused_mlp_kernel(const float* __restrict__ xyz,
                      const float* __restrict__ feats,
                      const float* __restrict__ b0, const float* __restrict__ g0, const float* __restrict__ e0,
                      const float* __restrict__ b1, const float* __restrict__ g1, const float* __restrict__ e1,
                      const float* __restrict__ b2, const float* __restrict__ g2, const float* __restrict__ e2) {
    extern __shared__ uint32_t smw[];
    __shared__ float sg[3][128], sb[3][128], se[3][128];
    __shared__ int   sj[128];
    __shared__ float sg3s[128][3];

    const int tid = threadIdx.x, lane = tid & 31, wid = tid >> 5;
    const int warp_m = wid >> 1, warp_n = wid & 1;   // warp_m 0..3, warp_n 0..1
    const int grp = lane >> 2, tig = lane & 3;
    const int tile = blockIdx.x, row0 = tile * 128;

    if (tid < 128) {
        sg[0][tid] = g0[tid]; sb[0][tid] = b0[tid]; se[0][tid] = e0[tid];
        sg[1][tid] = g1[tid]; sb[1][tid] = b1[tid]; se[1][tid] = e1[tid];
        sg[2][tid] = g2[tid]; sb[2][tid] = b2[tid]; se[2][tid] = e2[tid];
        int grow = row0 + tid;
        int bb = grow >> 12;
        int p = (grow & 4095) >> 4;
        int j = g_idx[grow];
        sj[tid] = j;
        int gp = bb * PP + p;
        #pragma unroll
        for (int d = 0; d < 3; d++)
            sg3s[tid][d] = __fdiv_rn(xyz[(size_t)(bb*KK + j)*3 + d] - g_newxyz[gp*3 + d], 0.3f);
    }
    __syncthreads();   // sj ready

    // stage B1 and B2 (resident); B0 streamed per tile
    {
        const uint4* s1 = (const uint4*)g_w1h;
        uint4* d1 = (uint4*)(smw + 8192);
        for (int q = tid; q < 2048; q += 256) d1[q] = s1[q];
        const uint4* s2 = (const uint4*)g_w2h;
        uint4* d2 = (uint4*)(smw + 16384);
        for (int q = tid; q < 2048; q += 256) d2[q] = s2[q];
    }

    const int ar = tid >> 1, h = tid & 1;   // ar 0..127
    const float4* frow4 = (const float4*)(feats + (size_t)((row0 >> 12) * KK + sj[ar]) * CC);
    const int m_tile_f = ar >> 4;           // 0..7
    const int R = ar & 15;
    const int grpa = R & 7;
    const int rowhi = R >> 3;

    // prefill: B0 tile 0 -> slot 0; A tile 0 -> Ach slot 0
    {
        ((uint4*)smw)[tid] = ((const uint4*)g_w0h)[tid];   // 256 uint4 = 1024 words
        uint32_t* Am = smw + 2048 + m_tile_f*128;
        float4 f0 = frow4[h*2], f1 = frow4[h*2 + 1];
        a16pair(Am, grpa, rowhi, h*4+0, packh2(f0.x, f0.y));
        a16pair(Am, grpa, rowhi, h*4+1, packh2(f0.z, f0.w));
        a16pair(Am, grpa, rowhi, h*4+2, packh2(f1.x, f1.y));
        a16pair(Am, grpa, rowhi, h*4+3, packh2(f1.z, f1.w));
    }
    __syncthreads();

    float acc[2][8][4];
    #pragma unroll
    for (int mt = 0; mt < 2; mt++)
        #pragma unroll
        for (int nt = 0; nt < 8; nt++)
            #pragma unroll
            for (int q = 0; q < 4; q++) acc[mt][nt][q] = 0.0f;

    // ---- layer 0: 17 k16-tiles, double-buffered A gather + B0 stream ----
    for (int kt = 0; kt < 17; kt++) {
        uint4 nb;
        float4 n0, n1;
        if (kt < 16) {
            nb = ((const uint4*)g_w0h)[(kt+1)*256 + tid];
            if (kt < 15) { n0 = frow4[(kt+1)*4 + h*2]; n1 = frow4[(kt+1)*4 + h*2 + 1]; }
        }

        const uint32_t* Ac = smw + 2048 + (kt & 1)*1024;
        const uint32_t* Bc = smw + (kt & 1)*1024;
        #pragma unroll
        for (int mt = 0; mt < 2; mt++) {
            uint4 av = *(const uint4*)&Ac[(warp_m*2 + mt)*128 + lane*4];
            #pragma unroll
            for (int nt = 0; nt < 8; nt++) {
                uint2 bv = *(const uint2*)&Bc[(warp_n*8 + nt)*64 + lane*2];
                mma16(acc[mt][nt], av.x, av.y, av.z, av.w, bv.x, bv.y);
            }
        }

        if (kt < 16) {
            ((uint4*)(smw + ((kt+1) & 1)*1024))[tid] = nb;
            uint32_t* Am = smw + 2048 + ((kt+1) & 1)*1024 + m_tile_f*128;
            if (kt < 15) {
                a16pair(Am, grpa, rowhi, h*4+0, packh2(n0.x, n0.y));
                a16pair(Am, grpa, rowhi, h*4+1, packh2(n0.z, n0.w));
                a16pair(Am, grpa, rowhi, h*4+2, packh2(n1.x, n1.y));
                a16pair(Am, grpa, rowhi, h*4+3, packh2(n1.z, n1.w));
            } else {                          // tile 16: xyz chunk
                uint32_t p0 = 0, p1 = 0;
                if (h == 0) {
                    p0 = packh2(sg3s[ar][0], sg3s[ar][1]);
                    p1 = packh2(sg3s[ar][2], 0.0f);
                }
                a16pair(Am, grpa, rowhi, h*4+0, p0);
                a16pair(Am, grpa, rowhi, h*4+1, p1);
                a16pair(Am, grpa, rowhi, h*4+2, 0u);
                a16pair(Am, grpa, rowhi, h*4+3, 0u);
            }
        }
        __syncthreads();
    }

    // epilogue helper: next layer's fp16 A-frag into dstw, zero acc
    auto epi16 = [&](uint32_t* dstw, int li) {
        #pragma unroll
        for (int mt = 0; mt < 2; mt++) {
            #pragma unroll
            for (int nt = 0; nt < 8; nt++) {
                int c = warp_n*64 + nt*8 + tig*2;
                float ga = sg[li][c], gb = sg[li][c+1];
                float ba = sb[li][c], bbv = sb[li][c+1];
                float ea = se[li][c], eb = se[li][c+1];
                float v0 = fmaxf(fmaf(ga, acc[mt][nt][0] + ba, ea), 0.0f);
                float v1 = fmaxf(fmaf(gb, acc[mt][nt][1] + bbv, eb), 0.0f);
                float v2 = fmaxf(fmaf(ga, acc[mt][nt][2] + ba, ea), 0.0f);
                float v3 = fmaxf(fmaf(gb, acc[mt][nt][3] + bbv, eb), 0.0f);
                int k_tile = warp_n*4 + (nt >> 1);
                uint32_t* p = dstw + ((warp_m*2 + mt)*8 + k_tile)*128 + (grp*4 + tig)*4 + (nt & 1)*2;
                *(uint2*)p = make_uint2(packh2(v0, v1), packh2(v2, v3));
                acc[mt][nt][0] = 0.f; acc[mt][nt][1] = 0.f; acc[mt][nt][2] = 0.f; acc[mt][nt][3] = 0.f;
            }
        }
    };

    epi16(smw, 0);            // A_L1 over R1 [0,8192)
    __syncthreads();

    // ---- layer 1: A_L1 @ smw, B1 @ smw+8192 ----
    #pragma unroll
    for (int ks = 0; ks < 8; ks++) {
        #pragma unroll
        for (int mt = 0; mt < 2; mt++) {
            uint4 av = *(const uint4*)&smw[((warp_m*2 + mt)*8 + ks)*128 + lane*4];
            #pragma unroll
            for (int nt = 0; nt < 8; nt++) {
                uint2 bv = *(const uint2*)&smw[8192 + ks*1024 + (warp_n*8 + nt)*64 + lane*2];
                mma16(acc[mt][nt], av.x, av.y, av.z, av.w, bv.x, bv.y);
            }
        }
    }
    __syncthreads();          // all warps done reading B1/A_L1
    epi16(smw + 8192, 1);     // A_L2 over B1
    __syncthreads();

    // ---- layer 2: A_L2 @ smw+8192, B2 @ smw+16384 ----
    #pragma unroll
    for (int ks = 0; ks < 8; ks++) {
        #pragma unroll
        for (int mt = 0; mt < 2; mt++) {
            uint4 av = *(const uint4*)&smw[8192 + ((warp_m*2 + mt)*8 + ks)*128 + lane*4];
            #pragma unroll
            for (int nt = 0; nt < 8; nt++) {
                uint2 bv = *(const uint2*)&smw[16384 + ks*1024 + (warp_n*8 + nt)*64 + lane*2];
                mma16(acc[mt][nt], av.x, av.y, av.z, av.w, bv.x, bv.y);
            }
        }
    }

    // ---- maxpool epilogue (8 groups of 16 rows) ----
    #pragma unroll
    for (int mt = 0; mt < 2; mt++) {
        int gidx = tile*8 + warp_m*2 + mt;
        #pragma unroll
        for (int nt = 0; nt < 8; nt++) {
            int c = warp_n*64 + nt*8 + tig*2;
            float ga = sg[2][c], gb = sg[2][c+1];
            float ba = sb[2][c], bbv = sb[2][c+1];
            float ea = se[2][c], eb = se[2][c+1];
            float v0 = fmaxf(fmaf(ga, acc[mt][nt][0] + ba, ea), 0.0f);
            float v1 = fmaxf(fmaf(gb, acc[mt][nt][1] + bbv, eb), 0.0f);
            float v2 = fmaxf(fmaf(ga, acc[mt][nt][2] + ba, ea), 0.0f);
            float v3 = fmaxf(fmaf(gb, acc[mt][nt][3] + bbv, eb), 0.0f);
            float mA = fmaxf(v0, v2), mB = fmaxf(v1, v3);
            #pragma unroll
            for (int o = 4; o < 32; o <<= 1) {
                mA = fmaxf(mA, __shfl_xor_sync(0xffffffffu, mA, o));
                mB = fmaxf(mB, __shfl_xor_sync(0xffffffffu, mB, o));
            }
            if (grp == 0) {
                g_feat[(size_t)gidx*128 + c]     = mA;
                g_feat[(size_t)gidx*128 + c + 1] = mB;
            }
        }
    }
}

// ---------------- FC helpers (tf32 path) ----------------
__device__ __forceinline__ void afrag_sts4_fc(float* A, int m_tile, int kl0,
                                              int laneRow, int slotR, float4 v) {
    int ktl = kl0 >> 3;
    int kin0 = kl0 & 7;
    int base = (m_tile*16 + ktl)*128 + laneRow*16 + slotR + ((kin0 < 4) ? 0 : 2);
    A[base + 0]  = tf32r(v.x);
    A[base + 4]  = tf32r(v.y);
    A[base + 8]  = tf32r(v.z);
    A[base + 12] = tf32r(v.w);
}

// M=64 tile GEMM: each warp owns m_tile = warp_m (0..3), N-half = warp_n
__device__ __forceinline__ void mma_64(const float* Af, const float* Bst,
                                       float acc[8][4],
                                       int warp_m, int warp_n, int lane) {
    #pragma unroll
    for (int ks = 0; ks < 16; ks++) {
        float4 a0 = *(const float4*)&Af[(warp_m*16 + ks)*128 + lane*4];
        float2 bv[8];
        #pragma unroll
        for (int nt = 0; nt < 8; nt++)
            bv[nt] = *(const float2*)&Bst[((ks*16 + warp_n*8 + nt)*32 + lane)*2];
        #pragma unroll
        for (int nt = 0; nt < 8; nt++)
            mma8(acc[nt], (const float*)&a0, bv[nt].x, bv[nt].y);
    }
}

// ---------------- fused FC1+FC2+head, error-compensated tf32 (M=64, grid=128) ----------------
// smem floats: A_hi [0,8192), A_lo [8192,16384), Bst [16384,32768)  (128KB)
__global__ __launch_bounds__(256)
void fused_fc_kernel(const float* __restrict__ b1, const float* __restrict__ g1, const float* __restrict__ e1,
                     const float* __restrict__ b2, const float* __restrict__ g2, const float* __restrict__ e2,
                     const float* __restrict__ b3, const float* __restrict__ msz,
                     float* __restrict__ out) {
    extern __shared__ float sm[];
    float* A_hi = sm;
    float* A_lo = sm + 8192;
    float* Bst  = sm + 16384;
    __shared__ float sg1[128], sb1[128], se1[128], sg2[128], sb2[128], se2[128];
    __shared__ float sb3[128], sms[54];

    const int tid = threadIdx.x, lane = tid & 31, wid = tid >> 5;
    const int warp_m = wid >> 1, warp_n = wid & 1;
    const int grp = lane >> 2, tig = lane & 3;
    const int row0 = blockIdx.x * 64;

    if (tid < 128) {
        sg1[tid] = g1[tid]; sb1[tid] = b1[tid]; se1[tid] = e1[tid];
        sg2[tid] = g2[tid]; sb2[tid] = b2[tid]; se2[tid] = e2[tid];
        sb3[tid] = (tid < OUTC) ? b3[tid] : 0.0f;
    } else if (tid < 182) {
        sms[tid - 128] = msz[tid - 128];
    }

    const int ar = tid >> 2, h = tid & 3;
    const int m_tile_f = ar >> 4;
    const int R = ar & 15;
    const int laneRow = R & 7;
    const int slotR = (R < 8) ? 0 : 1;
    {
        const float4* frow4 = (const float4*)(g_feat + (size_t)(row0 + ar) * 128);
        #pragma unroll
        for (int j = 0; j < 8; j++) {
            float4 v = frow4[h*8 + j];
            float4 hi = make_float4(tf32r(v.x), tf32r(v.y), tf32r(v.z), tf32r(v.w));
            float4 lo = make_float4(v.x - hi.x, v.y - hi.y, v.z - hi.z, v.w - hi.w);
            afrag_sts4_fc(A_hi, m_tile_f, h*32 + j*4, laneRow, slotR, hi);
            afrag_sts4_fc(A_lo, m_tile_f, h*32 + j*4, laneRow, slotR, lo);
        }
    }

    float acc[8][4];
    #pragma unroll
    for (int nt = 0; nt < 8; nt++)
        #pragma unroll
        for (int q = 0; q < 4; q++) acc[nt][q] = 0.0f;

    auto stage = [&](const float* src) {
        const float4* s = (const float4*)src;
        float4* d = (float4*)Bst;
        #pragma unroll
        for (int q = 0; q < 16; q++) d[tid + q*256] = s[tid + q*256];
    };
    auto epi_hilo = [&](const float* sgp, const float* sbp, const float* sep) {
        const int la0 = grp*4 + ((2*tig) & 3);
        const int slot_hi = (tig < 2) ? 0 : 2;
        #pragma unroll
        for (int nt = 0; nt < 8; nt++) {
            int c = warp_n*64 + nt*8 + tig*2;
            float ga = sgp[c], gb = sgp[c+1], ba = sbp[c], bbv = sbp[c+1], ea = sep[c], eb = sep[c+1];
            float v0 = fminf(fmaxf(fmaf(ga, acc[nt][0] + ba, ea), 0.0f), 6.0f);
            float v1 = fminf(fmaxf(fmaf(gb, acc[nt][1] + bbv, eb), 0.0f), 6.0f);
            float v2 = fminf(fmaxf(fmaf(ga, acc[nt][2] + ba, ea), 0.0f), 6.0f);
            float v3 = fminf(fmaxf(fmaf(gb, acc[nt][3] + bbv, eb), 0.0f), 6.0f);
            float h0 = tf32r(v0), h1 = tf32r(v1), h2 = tf32r(v2), h3 = tf32r(v3);
            int kt = warp_n*8 + nt;
            float* pH = A_hi + (warp_m*16 + kt)*128 + la0*4 + slot_hi;
            float* pL = A_lo + (warp_m*16 + kt)*128 + la0*4 + slot_hi;
            *(float2*)pH       = make_float2(h0, h2);
            *(float2*)(pH + 4) = make_float2(h1, h3);
            *(float2*)pL       = make_float2(tf32r(v0 - h0), tf32r(v2 - h2));
            *(float2*)(pL + 4) = make_float2(tf32r(v1 - h1), tf32r(v3 - h3));
            acc[nt][0] = 0.f; acc[nt][1] = 0.f; acc[nt][2] = 0.f; acc[nt][3] = 0.f;
        }
    };

    // ---- FC1 ----
    stage(g_fw1f);
    __syncthreads();
    mma_64(A_hi, Bst, acc, warp_m, warp_n, lane);
    mma_64(A_lo, Bst, acc, warp_m, warp_n, lane);
    __syncthreads();
    stage(g_fl1f);
    __syncthreads();
    mma_64(A_hi, Bst, acc, warp_m, warp_n, lane);
    __syncthreads();
    epi_hilo(sg1, sb1, se1);
    __syncthreads();

    // ---- FC2 ----
    stage(g_fw2f);
    __syncthreads();
    mma_64(A_hi, Bst, acc, warp_m, warp_n, lane);
    mma_64(A_lo, Bst, acc, warp_m, warp_n, lane);
    __syncthreads();
    stage(g_fl2f);
    __syncthreads();
    mma_64(A_hi, Bst, acc, warp_m, warp_n, lane);
    __syncthreads();
    epi_hilo(sg2, sb2, se2);
    __syncthreads();

    // ---- head ----
    stage(g_fw3f);
    __syncthreads();
    mma_64(A_hi, Bst, acc, warp_m, warp_n, lane);
    mma_64(A_lo, Bst, acc, warp_m, warp_n, lane);
    __syncthreads();
    stage(g_fl3f);
    __syncthreads();
    mma_64(A_hi, Bst, acc, warp_m, warp_n, lane);

    const float HRS = (float)(3.14159265359 / 12.0);
    {
        int rA = row0 + warp_m*16 + grp;
        #pragma unroll
        for (int nt = 0; nt < 8; nt++) {
            int c0 = warp_n*64 + nt*8 + tig*2;
            #pragma unroll
            for (int q = 0; q < 4; q++) {
                int c = c0 + (q & 1);
                int r = (q < 2) ? rA : rA + 8;
                if (c >= OUTC) continue;
                float v = acc[nt][q] + sb3[c];
                if (c < 3)       out[O_CENTER + r*3 + c] = g_newxyz[r*3 + c] + v;
                else if (c < 5)  out[O_OBJ + r*2 + (c-3)] = v;
                else if (c < 17) out[O_HS + r*12 + (c-5)] = v;
                else if (c < 35) out[O_SS + r*18 + (c-17)] = v;
                else if (c < 47) { out[O_HRN + r*12 + (c-35)] = v; out[O_HR + r*12 + (c-35)] = v * HRS; }
                else if (c < 101){ int s = c - 47; out[O_SRN + r*54 + s] = v; out[O_SR + r*54 + s] = v * sms[s]; }
                else             out[O_SEM + r*18 + (c-101)] = v;
            }
        }
    }
}

// ---------------- launch ----------------
extern "C" void kernel_launch(void* const* d_in, const int* in_sizes, int n_in,
                              void* d_out, int out_size) {
    const float* xyz      = (const float*)d_in[0];
    const float* features = (const float*)d_in[1];
    const float* msz      = (const float*)d_in[2];
    const float* w0  = (const float*)d_in[3];
    const float* b0  = (const float*)d_in[4];
    const float* gm0 = (const float*)d_in[5];
    const float* be0 = (const float*)d_in[6];
    const float* wm1 = (const float*)d_in[7];
    const float* bm1 = (const float*)d_in[8];
    const float* gm1 = (const float*)d_in[9];
    const float* bem1= (const float*)d_in[10];
    const float* wm2 = (const float*)d_in[11];
    const float* bm2 = (const float*)d_in[12];
    const float* gm2 = (const float*)d_in[13];
    const float* bem2= (const float*)d_in[14];
    const float* w1  = (const float*)d_in[15];
    const float* b1  = (const float*)d_in[16];
    const float* g1  = (const float*)d_in[17];
    const float* be1 = (const float*)d_in[18];
    const float* w2  = (const float*)d_in[19];
    const float* b2  = (const float*)d_in[20];
    const float* g2  = (const float*)d_in[21];
    const float* be2 = (const float*)d_in[22];
    const float* w3  = (const float*)d_in[23];
    const float* b3  = (const float*)d_in[24];
    float* out = (float*)d_out;

    cudaFuncSetAttribute(fused_mlp_kernel, cudaFuncAttributeMaxDynamicSharedMemorySize, 98304);
    cudaFuncSetAttribute(fused_fc_kernel,  cudaFuncAttributeMaxDynamicSharedMemorySize, 131072);

    fps_prep_kernel<<<148, 128>>>(xyz, w0, wm1, wm2, w1, w2, w3, out);
    bq_kernel<<<BB, 1024>>>(xyz);
    fused_mlp_kernel<<<NROWS/128, 256, 98304>>>(xyz, features,
                                                b0, gm0, be0,
                                                bm1, gm1, bem1,
                                                bm2, gm2, bem2);
    fused_fc_kernel<<<NG/64, 256, 131072>>>(b1, g1, be1, b2, g2, be2, b3, msz, out);
}

// round 16
// speedup vs baseline: 1.6447x; 1.0378x over previous
#include <cuda_runtime.h>
#include <cuda_fp16.h>
#include <cstdint>

#define BB    32
#define KK    1024
#define CC    256
#define PP    256
#define NSAMP 16
#define NROWS (BB*PP*NSAMP)   // 131072
#define NG    (BB*PP)         // 8192
#define HID   128
#define OUTC  119

// output segment offsets (floats): obj, center, hs, hrn, hr, ss, srn, sr, sem, new_xyz, inds
#define O_OBJ    0
#define O_CENTER 16384
#define O_HS     40960
#define O_HRN    139264
#define O_HR     237568
#define O_SS     335872
#define O_SRN    483328
#define O_SR     925696
#define O_SEM    1368064
#define O_NEWXYZ 1515520
#define O_INDS   1540096

// ---------------- scratch ----------------
__device__ int   g_inds[NG];
__device__ float g_newxyz[NG*3];
__device__ int   g_idx[NROWS];
__device__ __align__(16) float g_feat[NG*HID];
// fp16 MLP weights in m16n8k16 B-fragment layout (word = uint32 = 2 halfs)
__device__ __align__(16) uint32_t g_w0h[17*16*32*2];  // K=272 (k 0..255=feats, 256..258=xyz, rest 0)
__device__ __align__(16) uint32_t g_w1h[8*16*32*2];
__device__ __align__(16) uint32_t g_w2h[8*16*32*2];
// fp16 FC weights, hi + lo residual, m16n8k16 B-fragment layout
__device__ __align__(16) uint32_t g_fh1h[8192], g_fl1h[8192];
__device__ __align__(16) uint32_t g_fh2h[8192], g_fl2h[8192];
__device__ __align__(16) uint32_t g_fh3h[8192], g_fl3h[8192];  // head, N padded 119->128

__device__ __forceinline__ float tf32r(float v) {
    float o;
    asm("cvt.rna.tf32.f32 %0, %1;" : "=f"(o) : "f"(v));
    return o;
}
__device__ __forceinline__ uint32_t packh2(float a, float b) {
    __half2 h = __floats2half2_rn(a, b);
    return *(uint32_t*)&h;
}
__device__ __forceinline__ uint32_t redux_max_u32(uint32_t v) {
    uint32_t r;
    asm volatile("redux.sync.max.u32 %0, %1, 0xffffffff;" : "=r"(r) : "r"(v));
    return r;
}
__device__ __forceinline__ uint32_t redux_min_u32(uint32_t v) {
    uint32_t r;
    asm volatile("redux.sync.min.u32 %0, %1, 0xffffffff;" : "=r"(r) : "r"(v));
    return r;
}

// fp16 mma m16n8k16
__device__ __forceinline__ void mma16(float c[4], uint32_t a0, uint32_t a1, uint32_t a2, uint32_t a3,
                                      uint32_t b0, uint32_t b1) {
    asm volatile(
        "mma.sync.aligned.m16n8k16.row.col.f32.f16.f16.f32 "
        "{%0,%1,%2,%3}, {%4,%5,%6,%7}, {%8,%9}, {%0,%1,%2,%3};\n"
        : "+f"(c[0]), "+f"(c[1]), "+f"(c[2]), "+f"(c[3])
        : "r"(a0), "r"(a1), "r"(a2), "r"(a3), "r"(b0), "r"(b1));
}

// fp16 B-fragment scatter (k16 tiles); writes one half
__device__ __forceinline__ void bfrag16_store(uint32_t* dst, int k, int n, __half v) {
    int kt = k >> 4, kin = k & 15, ntl = n >> 3, gq = n & 7;
    int lane = gq*4 + ((kin >> 1) & 3), reg = kin >> 3;
    __half* p = (__half*)&dst[((kt*16 + ntl)*32 + lane)*2 + reg];
    p[k & 1] = v;
}

// fp16 A-fragment pair store
__device__ __forceinline__ void a16pair(uint32_t* frag_mbase, int grp, int rowhi, int kp, uint32_t packed) {
    frag_mbase[(grp*4 + (kp & 3))*4 + ((kp & 4) ? 2 : 0) + rowhi] = packed;
}

// ---------------- FPS (blocks 0..31: 2 warps, 16 pts/thread) + weight prep (32..147) ----------------
__global__ __launch_bounds__(128)
void fps_prep_kernel(const float* __restrict__ xyz,
                     const float* __restrict__ w0,
                     const float* __restrict__ wm1,
                     const float* __restrict__ wm2,
                     const float* __restrict__ w1,
                     const float* __restrict__ w2,
                     const float* __restrict__ w3,
                     float* __restrict__ out) {
    __shared__ float4 sp4[KK];
    __shared__ uint2  swc[2][2];
    __shared__ short  s_sel[PP];

    if (blockIdx.x >= 32) {
        for (int i = (blockIdx.x - 32) * 128 + threadIdx.x; i < 116736; i += 116 * 128) {
            if (i < 34816) {             // w0h: K permuted+padded to 272
                int kd = i >> 7, n = i & 127;
                float v = 0.0f;
                if (kd < 256)      v = w0[(size_t)(kd + 3)*128 + n];
                else if (kd < 259) v = w0[(size_t)(kd - 256)*128 + n];
                bfrag16_store(g_w0h, kd, n, __float2half_rn(v));
            } else if (i < 51200) {
                int j = i - 34816; int k = j >> 7, n = j & 127;
                bfrag16_store(g_w1h, k, n, __float2half_rn(wm1[j]));
            } else if (i < 67584) {
                int j = i - 51200; int k = j >> 7, n = j & 127;
                bfrag16_store(g_w2h, k, n, __float2half_rn(wm2[j]));
            } else if (i < 83968) {
                int j = i - 67584; int k = j >> 7, n = j & 127;
                float w = w1[j];
                __half hh = __float2half_rn(w);
                bfrag16_store(g_fh1h, k, n, hh);
                bfrag16_store(g_fl1h, k, n, __float2half_rn(w - __half2float(hh)));
            } else if (i < 100352) {
                int j = i - 83968; int k = j >> 7, n = j & 127;
                float w = w2[j];
                __half hh = __float2half_rn(w);
                bfrag16_store(g_fh2h, k, n, hh);
                bfrag16_store(g_fl2h, k, n, __float2half_rn(w - __half2float(hh)));
            } else {
                int j = i - 100352; int k = j >> 7, n = j & 127;
                float w = (n < OUTC) ? w3[(size_t)k*OUTC + n] : 0.0f;
                __half hh = __float2half_rn(w);
                bfrag16_store(g_fh3h, k, n, hh);
                bfrag16_store(g_fl3h, k, n, __float2half_rn(w - __half2float(hh)));
            }
        }
        return;
    }

    const int b = blockIdx.x;
    const int t = threadIdx.x;
    const float* xb = xyz + (size_t)b * KK * 3;

    for (int i = t; i < KK; i += 128)
        sp4[i] = make_float4(xb[i*3+0], xb[i*3+1], xb[i*3+2], 0.0f);
    if (t == 0) s_sel[0] = 0;
    __syncthreads();
    if (t >= 64) return;

    const int w = t >> 5, lane = t & 31;

    float px[16], py[16], pz[16], dist[16];
    #pragma unroll
    for (int q = 0; q < 16; q++) {
        float4 p = sp4[t*16 + q];
        px[q] = p.x; py[q] = p.y; pz[q] = p.z;
        dist[q] = 1e10f;
    }
    float4 lp = sp4[0];

    for (int it = 1; it < PP; it++) {
        float best = -1.0f; int bidx = 0;
        #pragma unroll
        for (int q = 0; q < 16; q++) {
            float dx = px[q] - lp.x, dy = py[q] - lp.y, dz = pz[q] - lp.z;
            float d = fmaf(dz, dz, fmaf(dy, dy, dx*dx));
            d = fminf(dist[q], d);
            dist[q] = d;
            if (d > best) { best = d; bidx = t*16 + q; }
        }
        uint32_t mv = redux_max_u32(__float_as_uint(best));
        uint32_t cand = (__float_as_uint(best) == mv) ? (uint32_t)bidx : 0xFFFFFFFFu;
        uint32_t widx = redux_min_u32(cand);

        if (lane == 0) swc[it & 1][w] = make_uint2(mv, widx);
        __syncthreads();

        uint2 c0 = swc[it & 1][0];
        uint2 c1 = swc[it & 1][1];
        uint32_t bi = (c1.x > c0.x || (c1.x == c0.x && c1.y < c0.y)) ? c1.y : c0.y;
        lp = sp4[bi];
        if (t == 0) s_sel[it] = (short)bi;
    }
    __syncthreads();

    for (int e = t; e < PP; e += 64) {
        int ci = s_sel[e];
        g_inds[b*PP + e] = ci;
        out[O_INDS + b*PP + e] = (float)ci;
        float4 c = sp4[ci];
        int base = (b*PP + e)*3;
        g_newxyz[base+0] = c.x; g_newxyz[base+1] = c.y; g_newxyz[base+2] = c.z;
        out[O_NEWXYZ + base + 0] = c.x;
        out[O_NEWXYZ + base + 1] = c.y;
        out[O_NEWXYZ + base + 2] = c.z;
    }
}

// ---------------- ball query (separate launch, wide parallelism) ----------------
__global__ void bq_kernel(const float* __restrict__ xyz) {
    __shared__ float4 sp4[KK];
    const int b = blockIdx.x;
    const int t = threadIdx.x;   // 1024
    const float* xb = xyz + (size_t)b * KK * 3;
    sp4[t] = make_float4(xb[t*3+0], xb[t*3+1], xb[t*3+2], 0.0f);
    __syncthreads();
    if (t >= PP) return;

    float4 qp = sp4[g_inds[b*PP + t]];
    int buf[NSAMP]; int cnt = 0;
    #pragma unroll 4
    for (int j = 0; j < KK; j++) {
        float4 p = sp4[j];
        float dx = qp.x - p.x, dy = qp.y - p.y, dz = qp.z - p.z;
        float d = fmaf(dz, dz, fmaf(dy, dy, dx*dx));
        if (d < 0.09f) { if (cnt < NSAMP) buf[cnt] = j; cnt++; }
    }
    if (cnt == 0) { for (int s = 0; s < NSAMP; s++) buf[s] = KK - 1; }
    else { int c = cnt < NSAMP ? cnt : NSAMP; for (int s = c; s < NSAMP; s++) buf[s] = buf[0]; }
    const int gp = b*PP + t;
    #pragma unroll
    for (int s = 0; s < NSAMP; s++) g_idx[gp*NSAMP + s] = buf[s];
}

// ---------------- fused layer0+1+2+maxpool (fp16 mma, M=128, 256 threads, 2 CTA/SM) ----------------
// smem word map (uint32, total 24576 words = 96KB):
//   R1 [0, 8192):  L0 phase: B0 ring 2x1024 @[0,2048), Ach ring 2x1024 @[2048,4096)
//                  after L0: A_L1 (8192 words)
//   R2 [8192, 16384): B1; after L1: A_L2
//   R3 [16384, 24576): B2
__global__ __launch_bounds__(256, 2)
void fused_mlp_kernel(const float* __restrict__ xyz,
                      const float* __restrict__ feats,
                      const float* __restrict__ b0, const float* __restrict__ g0, const float* __restrict__ e0,
                      const float* __restrict__ b1, const float* __restrict__ g1, const float* __restrict__ e1,
                      const float* __restrict__ b2, const float* __restrict__ g2, const float* __restrict__ e2) {
    extern __shared__ uint32_t smw[];
    __shared__ float sg[3][128], sb[3][128], se[3][128];
    __shared__ int   sj[128];
    __shared__ float sg3s[128][3];

    const int tid = threadIdx.x, lane = tid & 31, wid = tid >> 5;
    const int warp_m = wid >> 1, warp_n = wid & 1;   // warp_m 0..3, warp_n 0..1
    const int grp = lane >> 2, tig = lane & 3;
    const int tile = blockIdx.x, row0 = tile * 128;

    if (tid < 128) {
        sg[0][tid] = g0[tid]; sb[0][tid] = b0[tid]; se[0][tid] = e0[tid];
        sg[1][tid] = g1[tid]; sb[1][tid] = b1[tid]; se[1][tid] = e1[tid];
        sg[2][tid] = g2[tid]; sb[2][tid] = b2[tid]; se[2][tid] = e2[tid];
        int grow = row0 + tid;
        int bb = grow >> 12;
        int p = (grow & 4095) >> 4;
        int j = g_idx[grow];
        sj[tid] = j;
        int gp = bb * PP + p;
        #pragma unroll
        for (int d = 0; d < 3; d++)
            sg3s[tid][d] = __fdiv_rn(xyz[(size_t)(bb*KK + j)*3 + d] - g_newxyz[gp*3 + d], 0.3f);
    }
    __syncthreads();   // sj ready

    // stage B1 and B2 (resident); B0 streamed per tile
    {
        const uint4* s1 = (const uint4*)g_w1h;
        uint4* d1 = (uint4*)(smw + 8192);
        for (int q = tid; q < 2048; q += 256) d1[q] = s1[q];
        const uint4* s2 = (const uint4*)g_w2h;
        uint4* d2 = (uint4*)(smw + 16384);
        for (int q = tid; q < 2048; q += 256) d2[q] = s2[q];
    }

    const int ar = tid >> 1, h = tid & 1;   // ar 0..127
    const float4* frow4 = (const float4*)(feats + (size_t)((row0 >> 12) * KK + sj[ar]) * CC);
    const int m_tile_f = ar >> 4;           // 0..7
    const int R = ar & 15;
    const int grpa = R & 7;
    const int rowhi = R >> 3;

    // prefill: B0 tile 0 -> slot 0; A tile 0 -> Ach slot 0
    {
        ((uint4*)smw)[tid] = ((const uint4*)g_w0h)[tid];   // 256 uint4 = 1024 words
        uint32_t* Am = smw + 2048 + m_tile_f*128;
        float4 f0 = frow4[h*2], f1 = frow4[h*2 + 1];
        a16pair(Am, grpa, rowhi, h*4+0, packh2(f0.x, f0.y));
        a16pair(Am, grpa, rowhi, h*4+1, packh2(f0.z, f0.w));
        a16pair(Am, grpa, rowhi, h*4+2, packh2(f1.x, f1.y));
        a16pair(Am, grpa, rowhi, h*4+3, packh2(f1.z, f1.w));
    }
    __syncthreads();

    float acc[2][8][4];
    #pragma unroll
    for (int mt = 0; mt < 2; mt++)
        #pragma unroll
        for (int nt = 0; nt < 8; nt++)
            #pragma unroll
            for (int q = 0; q < 4; q++) acc[mt][nt][q] = 0.0f;

    // ---- layer 0: 17 k16-tiles, double-buffered A gather + B0 stream ----
    for (int kt = 0; kt < 17; kt++) {
        uint4 nb;
        float4 n0, n1;
        if (kt < 16) {
            nb = ((const uint4*)g_w0h)[(kt+1)*256 + tid];
            if (kt < 15) { n0 = frow4[(kt+1)*4 + h*2]; n1 = frow4[(kt+1)*4 + h*2 + 1]; }
        }

        const uint32_t* Ac = smw + 2048 + (kt & 1)*1024;
        const uint32_t* Bc = smw + (kt & 1)*1024;
        #pragma unroll
        for (int mt = 0; mt < 2; mt++) {
            uint4 av = *(const uint4*)&Ac[(warp_m*2 + mt)*128 + lane*4];
            #pragma unroll
            for (int nt = 0; nt < 8; nt++) {
                uint2 bv = *(const uint2*)&Bc[(warp_n*8 + nt)*64 + lane*2];
                mma16(acc[mt][nt], av.x, av.y, av.z, av.w, bv.x, bv.y);
            }
        }

        if (kt < 16) {
            ((uint4*)(smw + ((kt+1) & 1)*1024))[tid] = nb;
            uint32_t* Am = smw + 2048 + ((kt+1) & 1)*1024 + m_tile_f*128;
            if (kt < 15) {
                a16pair(Am, grpa, rowhi, h*4+0, packh2(n0.x, n0.y));
                a16pair(Am, grpa, rowhi, h*4+1, packh2(n0.z, n0.w));
                a16pair(Am, grpa, rowhi, h*4+2, packh2(n1.x, n1.y));
                a16pair(Am, grpa, rowhi, h*4+3, packh2(n1.z, n1.w));
            } else {                          // tile 16: xyz chunk
                uint32_t p0 = 0, p1 = 0;
                if (h == 0) {
                    p0 = packh2(sg3s[ar][0], sg3s[ar][1]);
                    p1 = packh2(sg3s[ar][2], 0.0f);
                }
                a16pair(Am, grpa, rowhi, h*4+0, p0);
                a16pair(Am, grpa, rowhi, h*4+1, p1);
                a16pair(Am, grpa, rowhi, h*4+2, 0u);
                a16pair(Am, grpa, rowhi, h*4+3, 0u);
            }
        }
        __syncthreads();
    }

    // epilogue helper: next layer's fp16 A-frag into dstw, zero acc
    auto epi16 = [&](uint32_t* dstw, int li) {
        #pragma unroll
        for (int mt = 0; mt < 2; mt++) {
            #pragma unroll
            for (int nt = 0; nt < 8; nt++) {
                int c = warp_n*64 + nt*8 + tig*2;
                float ga = sg[li][c], gb = sg[li][c+1];
                float ba = sb[li][c], bbv = sb[li][c+1];
                float ea = se[li][c], eb = se[li][c+1];
                float v0 = fmaxf(fmaf(ga, acc[mt][nt][0] + ba, ea), 0.0f);
                float v1 = fmaxf(fmaf(gb, acc[mt][nt][1] + bbv, eb), 0.0f);
                float v2 = fmaxf(fmaf(ga, acc[mt][nt][2] + ba, ea), 0.0f);
                float v3 = fmaxf(fmaf(gb, acc[mt][nt][3] + bbv, eb), 0.0f);
                int k_tile = warp_n*4 + (nt >> 1);
                uint32_t* p = dstw + ((warp_m*2 + mt)*8 + k_tile)*128 + (grp*4 + tig)*4 + (nt & 1)*2;
                *(uint2*)p = make_uint2(packh2(v0, v1), packh2(v2, v3));
                acc[mt][nt][0] = 0.f; acc[mt][nt][1] = 0.f; acc[mt][nt][2] = 0.f; acc[mt][nt][3] = 0.f;
            }
        }
    };

    epi16(smw, 0);            // A_L1 over R1 [0,8192)
    __syncthreads();

    // ---- layer 1: A_L1 @ smw, B1 @ smw+8192 ----
    #pragma unroll
    for (int ks = 0; ks < 8; ks++) {
        #pragma unroll
        for (int mt = 0; mt < 2; mt++) {
            uint4 av = *(const uint4*)&smw[((warp_m*2 + mt)*8 + ks)*128 + lane*4];
            #pragma unroll
            for (int nt = 0; nt < 8; nt++) {
                uint2 bv = *(const uint2*)&smw[8192 + ks*1024 + (warp_n*8 + nt)*64 + lane*2];
                mma16(acc[mt][nt], av.x, av.y, av.z, av.w, bv.x, bv.y);
            }
        }
    }
    __syncthreads();          // all warps done reading B1/A_L1
    epi16(smw + 8192, 1);     // A_L2 over B1
    __syncthreads();

    // ---- layer 2: A_L2 @ smw+8192, B2 @ smw+16384 ----
    #pragma unroll
    for (int ks = 0; ks < 8; ks++) {
        #pragma unroll
        for (int mt = 0; mt < 2; mt++) {
            uint4 av = *(const uint4*)&smw[8192 + ((warp_m*2 + mt)*8 + ks)*128 + lane*4];
            #pragma unroll
            for (int nt = 0; nt < 8; nt++) {
                uint2 bv = *(const uint2*)&smw[16384 + ks*1024 + (warp_n*8 + nt)*64 + lane*2];
                mma16(acc[mt][nt], av.x, av.y, av.z, av.w, bv.x, bv.y);
            }
        }
    }

    // ---- maxpool epilogue (8 groups of 16 rows) ----
    #pragma unroll
    for (int mt = 0; mt < 2; mt++) {
        int gidx = tile*8 + warp_m*2 + mt;
        #pragma unroll
        for (int nt = 0; nt < 8; nt++) {
            int c = warp_n*64 + nt*8 + tig*2;
            float ga = sg[2][c], gb = sg[2][c+1];
            float ba = sb[2][c], bbv = sb[2][c+1];
            float ea = se[2][c], eb = se[2][c+1];
            float v0 = fmaxf(fmaf(ga, acc[mt][nt][0] + ba, ea), 0.0f);
            float v1 = fmaxf(fmaf(gb, acc[mt][nt][1] + bbv, eb), 0.0f);
            float v2 = fmaxf(fmaf(ga, acc[mt][nt][2] + ba, ea), 0.0f);
            float v3 = fmaxf(fmaf(gb, acc[mt][nt][3] + bbv, eb), 0.0f);
            float mA = fmaxf(v0, v2), mB = fmaxf(v1, v3);
            #pragma unroll
            for (int o = 4; o < 32; o <<= 1) {
                mA = fmaxf(mA, __shfl_xor_sync(0xffffffffu, mA, o));
                mB = fmaxf(mB, __shfl_xor_sync(0xffffffffu, mB, o));
            }
            if (grp == 0) {
                g_feat[(size_t)gidx*128 + c]     = mA;
                g_feat[(size_t)gidx*128 + c + 1] = mB;
            }
        }
    }
}

// ---------------- fused FC1+FC2+head, error-compensated fp16 (M=64, grid=128, 2 CTA/SM) ----------------
// smem words: A_hi [0,4096), A_lo [4096,8192), Bst [8192,16384)  (64KB)
__global__ __launch_bounds__(256, 2)
void fused_fc_kernel(const float* __restrict__ b1, const float* __restrict__ g1, const float* __restrict__ e1,
                     const float* __restrict__ b2, const float* __restrict__ g2, const float* __restrict__ e2,
                     const float* __restrict__ b3, const float* __restrict__ msz,
                     float* __restrict__ out) {
    extern __shared__ uint32_t smf[];
    uint32_t* A_hi = smf;
    uint32_t* A_lo = smf + 4096;
    uint32_t* Bst  = smf + 8192;
    __shared__ float sg1[128], sb1[128], se1[128], sg2[128], sb2[128], se2[128];
    __shared__ float sb3[128], sms[54];

    const int tid = threadIdx.x, lane = tid & 31, wid = tid >> 5;
    const int warp_m = wid >> 1, warp_n = wid & 1;   // warp_m 0..3 = m16 tile
    const int grp = lane >> 2, tig = lane & 3;
    const int row0 = blockIdx.x * 64;

    if (tid < 128) {
        sg1[tid] = g1[tid]; sb1[tid] = b1[tid]; se1[tid] = e1[tid];
        sg2[tid] = g2[tid]; sb2[tid] = b2[tid]; se2[tid] = e2[tid];
        sb3[tid] = (tid < OUTC) ? b3[tid] : 0.0f;
    } else if (tid < 182) {
        sms[tid - 128] = msz[tid - 128];
    }

    // fill A_hi / A_lo from g_feat: 64 rows, 4 threads/row (32 cols each)
    const int ar = tid >> 2, h = tid & 3;
    const int m_tile_f = ar >> 4;
    const int R = ar & 15;
    const int grpa = R & 7;
    const int rowhi = R >> 3;
    {
        const float4* frow4 = (const float4*)(g_feat + (size_t)(row0 + ar) * 128);
        #pragma unroll
        for (int j = 0; j < 8; j++) {
            float4 v = frow4[h*8 + j];
            int c0 = h*32 + j*4;
            int ktile = c0 >> 4;
            int kp0 = (c0 & 15) >> 1;    // even
            float hx = __half2float(__float2half_rn(v.x));
            float hy = __half2float(__float2half_rn(v.y));
            float hz = __half2float(__float2half_rn(v.z));
            float hw = __half2float(__float2half_rn(v.w));
            uint32_t* bH = A_hi + (m_tile_f*8 + ktile)*128;
            uint32_t* bL = A_lo + (m_tile_f*8 + ktile)*128;
            a16pair(bH, grpa, rowhi, kp0,     packh2(v.x, v.y));
            a16pair(bH, grpa, rowhi, kp0 + 1, packh2(v.z, v.w));
            a16pair(bL, grpa, rowhi, kp0,     packh2(v.x - hx, v.y - hy));
            a16pair(bL, grpa, rowhi, kp0 + 1, packh2(v.z - hz, v.w - hw));
        }
    }

    float acc[8][4];
    #pragma unroll
    for (int nt = 0; nt < 8; nt++)
        #pragma unroll
        for (int q = 0; q < 4; q++) acc[nt][q] = 0.0f;

    auto stage = [&](const uint32_t* src) {
        const uint4* s = (const uint4*)src;
        uint4* d = (uint4*)Bst;
        #pragma unroll
        for (int q = 0; q < 8; q++) d[tid + q*256] = s[tid + q*256];
    };
    // one K=128 fp16 GEMM pass from A-frag + Bst
    auto mmaF = [&](const uint32_t* Af) {
        #pragma unroll
        for (int ks = 0; ks < 8; ks++) {
            uint4 av = *(const uint4*)&Af[(warp_m*8 + ks)*128 + lane*4];
            #pragma unroll
            for (int nt = 0; nt < 8; nt++) {
                uint2 bv = *(const uint2*)&Bst[ks*1024 + (warp_n*8 + nt)*64 + lane*2];
                mma16(acc[nt], av.x, av.y, av.z, av.w, bv.x, bv.y);
            }
        }
    };
    // compensated epilogue: relu6 affine -> fp16 hi/lo A-frags, zero acc
    auto epi_hilo = [&](const float* sgp, const float* sbp, const float* sep) {
        #pragma unroll
        for (int nt = 0; nt < 8; nt++) {
            int c = warp_n*64 + nt*8 + tig*2;
            float ga = sgp[c], gb = sgp[c+1], ba = sbp[c], bbv = sbp[c+1], ea = sep[c], eb = sep[c+1];
            float v0 = fminf(fmaxf(fmaf(ga, acc[nt][0] + ba, ea), 0.0f), 6.0f);
            float v1 = fminf(fmaxf(fmaf(gb, acc[nt][1] + bbv, eb), 0.0f), 6.0f);
            float v2 = fminf(fmaxf(fmaf(ga, acc[nt][2] + ba, ea), 0.0f), 6.0f);
            float v3 = fminf(fmaxf(fmaf(gb, acc[nt][3] + bbv, eb), 0.0f), 6.0f);
            float h0 = __half2float(__float2half_rn(v0));
            float h1 = __half2float(__float2half_rn(v1));
            float h2 = __half2float(__float2half_rn(v2));
            float h3 = __half2float(__float2half_rn(v3));
            int k_tile = warp_n*4 + (nt >> 1);
            uint32_t off = (warp_m*8 + k_tile)*128 + (grp*4 + tig)*4 + (nt & 1)*2;
            *(uint2*)&A_hi[off] = make_uint2(packh2(v0, v1), packh2(v2, v3));
            *(uint2*)&A_lo[off] = make_uint2(packh2(v0 - h0, v1 - h1), packh2(v2 - h2, v3 - h3));
            acc[nt][0] = 0.f; acc[nt][1] = 0.f; acc[nt][2] = 0.f; acc[nt][3] = 0.f;
        }
    };

    // ---- FC1 ----
    stage(g_fh1h);
    __syncthreads();
    mmaF(A_hi);
    mmaF(A_lo);
    __syncthreads();
    stage(g_fl1h);
    __syncthreads();
    mmaF(A_hi);
    __syncthreads();
    epi_hilo(sg1, sb1, se1);
    __syncthreads();

    // ---- FC2 ----
    stage(g_fh2h);
    __syncthreads();
    mmaF(A_hi);
    mmaF(A_lo);
    __syncthreads();
    stage(g_fl2h);
    __syncthreads();
    mmaF(A_hi);
    __syncthreads();
    epi_hilo(sg2, sb2, se2);
    __syncthreads();

    // ---- head ----
    stage(g_fh3h);
    __syncthreads();
    mmaF(A_hi);
    mmaF(A_lo);
    __syncthreads();
    stage(g_fl3h);
    __syncthreads();
    mmaF(A_hi);

    // head scatter from accumulator frags
    const float HRS = (float)(3.14159265359 / 12.0);
    {
        int rA = row0 + warp_m*16 + grp;
        #pragma unroll
        for (int nt = 0; nt < 8; nt++) {
            int c0 = warp_n*64 + nt*8 + tig*2;
            #pragma unroll
            for (int q = 0; q < 4; q++) {
                int c = c0 + (q & 1);
                int r = (q < 2) ? rA : rA + 8;
                if (c >= OUTC) continue;
                float v = acc[nt][q] + sb3[c];
                if (c < 3)       out[O_CENTER + r*3 + c] = g_newxyz[r*3 + c] + v;
                else if (c < 5)  out[O_OBJ + r*2 + (c-3)] = v;
                else if (c < 17) out[O_HS + r*12 + (c-5)] = v;
                else if (c < 35) out[O_SS + r*18 + (c-17)] = v;
                else if (c < 47) { out[O_HRN + r*12 + (c-35)] = v; out[O_HR + r*12 + (c-35)] = v * HRS; }
                else if (c < 101){ int s = c - 47; out[O_SRN + r*54 + s] = v; out[O_SR + r*54 + s] = v * sms[s]; }
                else             out[O_SEM + r*18 + (c-101)] = v;
            }
        }
    }
}

// ---------------- launch ----------------
extern "C" void kernel_launch(void* const* d_in, const int* in_sizes, int n_in,
                              void* d_out, int out_size) {
    const float* xyz      = (const float*)d_in[0];
    const float* features = (const float*)d_in[1];
    const float* msz      = (const float*)d_in[2];
    const float* w0  = (const float*)d_in[3];
    const float* b0  = (const float*)d_in[4];
    const float* gm0 = (const float*)d_in[5];
    const float* be0 = (const float*)d_in[6];
    const float* wm1 = (const float*)d_in[7];
    const float* bm1 = (const float*)d_in[8];
    const float* gm1 = (const float*)d_in[9];
    const float* bem1= (const float*)d_in[10];
    const float* wm2 = (const float*)d_in[11];
    const float* bm2 = (const float*)d_in[12];
    const float* gm2 = (const float*)d_in[13];
    const float* bem2= (const float*)d_in[14];
    const float* w1  = (const float*)d_in[15];
    const float* b1  = (const float*)d_in[16];
    const float* g1  = (const float*)d_in[17];
    const float* be1 = (const float*)d_in[18];
    const float* w2  = (const float*)d_in[19];
    const float* b2  = (const float*)d_in[20];
    const float* g2  = (const float*)d_in[21];
    const float* be2 = (const float*)d_in[22];
    const float* w3  = (const float*)d_in[23];
    const float* b3  = (const float*)d_in[24];
    float* out = (float*)d_out;

    cudaFuncSetAttribute(fused_mlp_kernel, cudaFuncAttributeMaxDynamicSharedMemorySize, 98304);
    cudaFuncSetAttribute(fused_fc_kernel,  cudaFuncAttributeMaxDynamicSharedMemorySize, 65536);

    fps_prep_kernel<<<148, 128>>>(xyz, w0, wm1, wm2, w1, w2, w3, out);
    bq_kernel<<<BB, 1024>>>(xyz);
    fused_mlp_kernel<<<NROWS/128, 256, 98304>>>(xyz, features,
                                                b0, gm0, be0,
                                                bm1, gm1, bem1,
                                                bm2, gm2, bem2);
    fused_fc_kernel<<<NG/64, 256, 65536>>>(b1, g1, be1, b2, g2, be2, b3, msz, out);
}

// round 17
// speedup vs baseline: 1.6959x; 1.0312x over previous
#include <cuda_runtime.h>
#include <cuda_fp16.h>
#include <cstdint>

#define BB    32
#define KK    1024
#define CC    256
#define PP    256
#define NSAMP 16
#define NROWS (BB*PP*NSAMP)   // 131072
#define NG    (BB*PP)         // 8192
#define HID   128
#define OUTC  119

// output segment offsets (floats): obj, center, hs, hrn, hr, ss, srn, sr, sem, new_xyz, inds
#define O_OBJ    0
#define O_CENTER 16384
#define O_HS     40960
#define O_HRN    139264
#define O_HR     237568
#define O_SS     335872
#define O_SRN    483328
#define O_SR     925696
#define O_SEM    1368064
#define O_NEWXYZ 1515520
#define O_INDS   1540096

// ---------------- scratch ----------------
__device__ int   g_inds[NG];
__device__ float g_newxyz[NG*3];
__device__ int   g_idx[NROWS];
__device__ __align__(16) float g_feat[NG*HID];
// fp16 MLP weights in m16n8k16 B-fragment layout (word = uint32 = 2 halfs)
__device__ __align__(16) uint32_t g_w0h[17*16*32*2];  // K=272 (k 0..255=feats, 256..258=xyz, rest 0)
__device__ __align__(16) uint32_t g_w1h[8*16*32*2];
__device__ __align__(16) uint32_t g_w2h[8*16*32*2];
// fp16 FC weights, hi + lo residual, m16n8k16 B-fragment layout
__device__ __align__(16) uint32_t g_fh1h[8192], g_fl1h[8192];
__device__ __align__(16) uint32_t g_fh2h[8192], g_fl2h[8192];
__device__ __align__(16) uint32_t g_fh3h[8192], g_fl3h[8192];  // head, N padded 119->128

__device__ __forceinline__ uint32_t packh2(float a, float b) {
    __half2 h = __floats2half2_rn(a, b);
    return *(uint32_t*)&h;
}
__device__ __forceinline__ uint32_t redux_max_u32(uint32_t v) {
    uint32_t r;
    asm volatile("redux.sync.max.u32 %0, %1, 0xffffffff;" : "=r"(r) : "r"(v));
    return r;
}
__device__ __forceinline__ uint32_t redux_min_u32(uint32_t v) {
    uint32_t r;
    asm volatile("redux.sync.min.u32 %0, %1, 0xffffffff;" : "=r"(r) : "r"(v));
    return r;
}

// fp16 mma m16n8k16
__device__ __forceinline__ void mma16(float c[4], uint32_t a0, uint32_t a1, uint32_t a2, uint32_t a3,
                                      uint32_t b0, uint32_t b1) {
    asm volatile(
        "mma.sync.aligned.m16n8k16.row.col.f32.f16.f16.f32 "
        "{%0,%1,%2,%3}, {%4,%5,%6,%7}, {%8,%9}, {%0,%1,%2,%3};\n"
        : "+f"(c[0]), "+f"(c[1]), "+f"(c[2]), "+f"(c[3])
        : "r"(a0), "r"(a1), "r"(a2), "r"(a3), "r"(b0), "r"(b1));
}

// fp16 B-fragment scatter (k16 tiles); writes one half
__device__ __forceinline__ void bfrag16_store(uint32_t* dst, int k, int n, __half v) {
    int kt = k >> 4, kin = k & 15, ntl = n >> 3, gq = n & 7;
    int lane = gq*4 + ((kin >> 1) & 3), reg = kin >> 3;
    __half* p = (__half*)&dst[((kt*16 + ntl)*32 + lane)*2 + reg];
    p[k & 1] = v;
}

// fp16 A-fragment pair store
__device__ __forceinline__ void a16pair(uint32_t* frag_mbase, int grp, int rowhi, int kp, uint32_t packed) {
    frag_mbase[(grp*4 + (kp & 3))*4 + ((kp & 4) ? 2 : 0) + rowhi] = packed;
}

// ---------------- FPS (blocks 0..31: 2 warps, 16 pts/thread) + weight prep (32..147) ----------------
__global__ __launch_bounds__(128)
void fps_prep_kernel(const float* __restrict__ xyz,
                     const float* __restrict__ w0,
                     const float* __restrict__ wm1,
                     const float* __restrict__ wm2,
                     const float* __restrict__ w1,
                     const float* __restrict__ w2,
                     const float* __restrict__ w3,
                     float* __restrict__ out) {
    __shared__ float4 sp4[KK];
    __shared__ uint2  swc[2][2];
    __shared__ short  s_sel[PP];

    if (blockIdx.x >= 32) {
        for (int i = (blockIdx.x - 32) * 128 + threadIdx.x; i < 116736; i += 116 * 128) {
            if (i < 34816) {             // w0h: K permuted+padded to 272
                int kd = i >> 7, n = i & 127;
                float v = 0.0f;
                if (kd < 256)      v = w0[(size_t)(kd + 3)*128 + n];
                else if (kd < 259) v = w0[(size_t)(kd - 256)*128 + n];
                bfrag16_store(g_w0h, kd, n, __float2half_rn(v));
            } else if (i < 51200) {
                int j = i - 34816; int k = j >> 7, n = j & 127;
                bfrag16_store(g_w1h, k, n, __float2half_rn(wm1[j]));
            } else if (i < 67584) {
                int j = i - 51200; int k = j >> 7, n = j & 127;
                bfrag16_store(g_w2h, k, n, __float2half_rn(wm2[j]));
            } else if (i < 83968) {
                int j = i - 67584; int k = j >> 7, n = j & 127;
                float w = w1[j];
                __half hh = __float2half_rn(w);
                bfrag16_store(g_fh1h, k, n, hh);
                bfrag16_store(g_fl1h, k, n, __float2half_rn(w - __half2float(hh)));
            } else if (i < 100352) {
                int j = i - 83968; int k = j >> 7, n = j & 127;
                float w = w2[j];
                __half hh = __float2half_rn(w);
                bfrag16_store(g_fh2h, k, n, hh);
                bfrag16_store(g_fl2h, k, n, __float2half_rn(w - __half2float(hh)));
            } else {
                int j = i - 100352; int k = j >> 7, n = j & 127;
                float w = (n < OUTC) ? w3[(size_t)k*OUTC + n] : 0.0f;
                __half hh = __float2half_rn(w);
                bfrag16_store(g_fh3h, k, n, hh);
                bfrag16_store(g_fl3h, k, n, __float2half_rn(w - __half2float(hh)));
            }
        }
        return;
    }

    const int b = blockIdx.x;
    const int t = threadIdx.x;
    const float* xb = xyz + (size_t)b * KK * 3;

    for (int i = t; i < KK; i += 128)
        sp4[i] = make_float4(xb[i*3+0], xb[i*3+1], xb[i*3+2], 0.0f);
    if (t == 0) s_sel[0] = 0;
    __syncthreads();
    if (t >= 64) return;

    const int w = t >> 5, lane = t & 31;

    float px[16], py[16], pz[16], dist[16];
    #pragma unroll
    for (int q = 0; q < 16; q++) {
        float4 p = sp4[t*16 + q];
        px[q] = p.x; py[q] = p.y; pz[q] = p.z;
        dist[q] = 1e10f;
    }
    float4 lp = sp4[0];

    for (int it = 1; it < PP; it++) {
        float best = -1.0f; int bidx = 0;
        #pragma unroll
        for (int q = 0; q < 16; q++) {
            float dx = px[q] - lp.x, dy = py[q] - lp.y, dz = pz[q] - lp.z;
            float d = fmaf(dz, dz, fmaf(dy, dy, dx*dx));
            d = fminf(dist[q], d);
            dist[q] = d;
            if (d > best) { best = d; bidx = t*16 + q; }
        }
        uint32_t mv = redux_max_u32(__float_as_uint(best));
        uint32_t cand = (__float_as_uint(best) == mv) ? (uint32_t)bidx : 0xFFFFFFFFu;
        uint32_t widx = redux_min_u32(cand);

        if (lane == 0) swc[it & 1][w] = make_uint2(mv, widx);
        __syncthreads();

        uint2 c0 = swc[it & 1][0];
        uint2 c1 = swc[it & 1][1];
        uint32_t bi = (c1.x > c0.x || (c1.x == c0.x && c1.y < c0.y)) ? c1.y : c0.y;
        lp = sp4[bi];
        if (t == 0) s_sel[it] = (short)bi;
    }
    __syncthreads();

    for (int e = t; e < PP; e += 64) {
        int ci = s_sel[e];
        g_inds[b*PP + e] = ci;
        out[O_INDS + b*PP + e] = (float)ci;
        float4 c = sp4[ci];
        int base = (b*PP + e)*3;
        g_newxyz[base+0] = c.x; g_newxyz[base+1] = c.y; g_newxyz[base+2] = c.z;
        out[O_NEWXYZ + base + 0] = c.x;
        out[O_NEWXYZ + base + 1] = c.y;
        out[O_NEWXYZ + base + 2] = c.z;
    }
}

// ---------------- ball query (separate launch, wide parallelism) ----------------
__global__ void bq_kernel(const float* __restrict__ xyz) {
    __shared__ float4 sp4[KK];
    const int b = blockIdx.x;
    const int t = threadIdx.x;   // 1024
    const float* xb = xyz + (size_t)b * KK * 3;
    sp4[t] = make_float4(xb[t*3+0], xb[t*3+1], xb[t*3+2], 0.0f);
    __syncthreads();
    if (t >= PP) return;

    float4 qp = sp4[g_inds[b*PP + t]];
    int buf[NSAMP]; int cnt = 0;
    #pragma unroll 4
    for (int j = 0; j < KK; j++) {
        float4 p = sp4[j];
        float dx = qp.x - p.x, dy = qp.y - p.y, dz = qp.z - p.z;
        float d = fmaf(dz, dz, fmaf(dy, dy, dx*dx));
        if (d < 0.09f) { if (cnt < NSAMP) buf[cnt] = j; cnt++; }
    }
    if (cnt == 0) { for (int s = 0; s < NSAMP; s++) buf[s] = KK - 1; }
    else { int c = cnt < NSAMP ? cnt : NSAMP; for (int s = c; s < NSAMP; s++) buf[s] = buf[0]; }
    const int gp = b*PP + t;
    #pragma unroll
    for (int s = 0; s < NSAMP; s++) g_idx[gp*NSAMP + s] = buf[s];
}

// ---------------- fused layer0+1+2+maxpool (fp16 mma, M=128, 256 threads, 2 CTA/SM) ----------------
// smem word map (uint32, total 24576 words = 96KB):
//   R1 [0, 8192):  L0 phase: B0 ring 2x1024 @[0,2048), Ach ring 2x1024 @[2048,4096)
//                  after L0: A_L1 (8192 words)
//   R2 [8192, 16384): B1; after L1: A_L2
//   R3 [16384, 24576): B2
__global__ __launch_bounds__(256, 2)
void fused_mlp_kernel(const float* __restrict__ xyz,
                      const float* __restrict__ feats,
                      const float* __restrict__ b0, const float* __restrict__ g0, const float* __restrict__ e0,
                      const float* __restrict__ b1, const float* __restrict__ g1, const float* __restrict__ e1,
                      const float* __restrict__ b2, const float* __restrict__ g2, const float* __restrict__ e2) {
    extern __shared__ uint32_t smw[];
    __shared__ float sg[3][128], sb[3][128], se[3][128];
    __shared__ int   sj[128];
    __shared__ float sg3s[128][3];

    const int tid = threadIdx.x, lane = tid & 31, wid = tid >> 5;
    const int warp_m = wid >> 1, warp_n = wid & 1;   // warp_m 0..3, warp_n 0..1
    const int grp = lane >> 2, tig = lane & 3;
    const int tile = blockIdx.x, row0 = tile * 128;

    if (tid < 128) {
        sg[0][tid] = g0[tid]; sb[0][tid] = b0[tid]; se[0][tid] = e0[tid];
        sg[1][tid] = g1[tid]; sb[1][tid] = b1[tid]; se[1][tid] = e1[tid];
        sg[2][tid] = g2[tid]; sb[2][tid] = b2[tid]; se[2][tid] = e2[tid];
        int grow = row0 + tid;
        int bb = grow >> 12;
        int p = (grow & 4095) >> 4;
        int j = g_idx[grow];
        sj[tid] = j;
        int gp = bb * PP + p;
        #pragma unroll
        for (int d = 0; d < 3; d++)
            sg3s[tid][d] = __fdiv_rn(xyz[(size_t)(bb*KK + j)*3 + d] - g_newxyz[gp*3 + d], 0.3f);
    }
    __syncthreads();   // sj ready

    // stage B1 and B2 (resident); B0 streamed per tile
    {
        const uint4* s1 = (const uint4*)g_w1h;
        uint4* d1 = (uint4*)(smw + 8192);
        for (int q = tid; q < 2048; q += 256) d1[q] = s1[q];
        const uint4* s2 = (const uint4*)g_w2h;
        uint4* d2 = (uint4*)(smw + 16384);
        for (int q = tid; q < 2048; q += 256) d2[q] = s2[q];
    }

    const int ar = tid >> 1, h = tid & 1;   // ar 0..127
    const float4* frow4 = (const float4*)(feats + (size_t)((row0 >> 12) * KK + sj[ar]) * CC);
    const int m_tile_f = ar >> 4;           // 0..7
    const int R = ar & 15;
    const int grpa = R & 7;
    const int rowhi = R >> 3;

    // prefill: B0 tile 0 -> slot 0; A tile 0 -> Ach slot 0
    {
        ((uint4*)smw)[tid] = ((const uint4*)g_w0h)[tid];   // 256 uint4 = 1024 words
        uint32_t* Am = smw + 2048 + m_tile_f*128;
        float4 f0 = frow4[h*2], f1 = frow4[h*2 + 1];
        a16pair(Am, grpa, rowhi, h*4+0, packh2(f0.x, f0.y));
        a16pair(Am, grpa, rowhi, h*4+1, packh2(f0.z, f0.w));
        a16pair(Am, grpa, rowhi, h*4+2, packh2(f1.x, f1.y));
        a16pair(Am, grpa, rowhi, h*4+3, packh2(f1.z, f1.w));
    }
    __syncthreads();

    float acc[2][8][4];
    #pragma unroll
    for (int mt = 0; mt < 2; mt++)
        #pragma unroll
        for (int nt = 0; nt < 8; nt++)
            #pragma unroll
            for (int q = 0; q < 4; q++) acc[mt][nt][q] = 0.0f;

    // ---- layer 0: 17 k16-tiles, double-buffered A gather + B0 stream ----
    for (int kt = 0; kt < 17; kt++) {
        uint4 nb;
        float4 n0, n1;
        if (kt < 16) {
            nb = ((const uint4*)g_w0h)[(kt+1)*256 + tid];
            if (kt < 15) { n0 = frow4[(kt+1)*4 + h*2]; n1 = frow4[(kt+1)*4 + h*2 + 1]; }
        }

        const uint32_t* Ac = smw + 2048 + (kt & 1)*1024;
        const uint32_t* Bc = smw + (kt & 1)*1024;
        #pragma unroll
        for (int mt = 0; mt < 2; mt++) {
            uint4 av = *(const uint4*)&Ac[(warp_m*2 + mt)*128 + lane*4];
            #pragma unroll
            for (int nt = 0; nt < 8; nt++) {
                uint2 bv = *(const uint2*)&Bc[(warp_n*8 + nt)*64 + lane*2];
                mma16(acc[mt][nt], av.x, av.y, av.z, av.w, bv.x, bv.y);
            }
        }

        if (kt < 16) {
            ((uint4*)(smw + ((kt+1) & 1)*1024))[tid] = nb;
            uint32_t* Am = smw + 2048 + ((kt+1) & 1)*1024 + m_tile_f*128;
            if (kt < 15) {
                a16pair(Am, grpa, rowhi, h*4+0, packh2(n0.x, n0.y));
                a16pair(Am, grpa, rowhi, h*4+1, packh2(n0.z, n0.w));
                a16pair(Am, grpa, rowhi, h*4+2, packh2(n1.x, n1.y));
                a16pair(Am, grpa, rowhi, h*4+3, packh2(n1.z, n1.w));
            } else {                          // tile 16: xyz chunk
                uint32_t p0 = 0, p1 = 0;
                if (h == 0) {
                    p0 = packh2(sg3s[ar][0], sg3s[ar][1]);
                    p1 = packh2(sg3s[ar][2], 0.0f);
                }
                a16pair(Am, grpa, rowhi, h*4+0, p0);
                a16pair(Am, grpa, rowhi, h*4+1, p1);
                a16pair(Am, grpa, rowhi, h*4+2, 0u);
                a16pair(Am, grpa, rowhi, h*4+3, 0u);
            }
        }
        __syncthreads();
    }

    // epilogue helper: next layer's fp16 A-frag into dstw, zero acc
    auto epi16 = [&](uint32_t* dstw, int li) {
        #pragma unroll
        for (int mt = 0; mt < 2; mt++) {
            #pragma unroll
            for (int nt = 0; nt < 8; nt++) {
                int c = warp_n*64 + nt*8 + tig*2;
                float ga = sg[li][c], gb = sg[li][c+1];
                float ba = sb[li][c], bbv = sb[li][c+1];
                float ea = se[li][c], eb = se[li][c+1];
                float v0 = fmaxf(fmaf(ga, acc[mt][nt][0] + ba, ea), 0.0f);
                float v1 = fmaxf(fmaf(gb, acc[mt][nt][1] + bbv, eb), 0.0f);
                float v2 = fmaxf(fmaf(ga, acc[mt][nt][2] + ba, ea), 0.0f);
                float v3 = fmaxf(fmaf(gb, acc[mt][nt][3] + bbv, eb), 0.0f);
                int k_tile = warp_n*4 + (nt >> 1);
                uint32_t* p = dstw + ((warp_m*2 + mt)*8 + k_tile)*128 + (grp*4 + tig)*4 + (nt & 1)*2;
                *(uint2*)p = make_uint2(packh2(v0, v1), packh2(v2, v3));
                acc[mt][nt][0] = 0.f; acc[mt][nt][1] = 0.f; acc[mt][nt][2] = 0.f; acc[mt][nt][3] = 0.f;
            }
        }
    };

    epi16(smw, 0);            // A_L1 over R1 [0,8192)
    __syncthreads();

    // ---- layer 1: A_L1 @ smw, B1 @ smw+8192 ----
    #pragma unroll
    for (int ks = 0; ks < 8; ks++) {
        #pragma unroll
        for (int mt = 0; mt < 2; mt++) {
            uint4 av = *(const uint4*)&smw[((warp_m*2 + mt)*8 + ks)*128 + lane*4];
            #pragma unroll
            for (int nt = 0; nt < 8; nt++) {
                uint2 bv = *(const uint2*)&smw[8192 + ks*1024 + (warp_n*8 + nt)*64 + lane*2];
                mma16(acc[mt][nt], av.x, av.y, av.z, av.w, bv.x, bv.y);
            }
        }
    }
    __syncthreads();          // all warps done reading B1/A_L1
    epi16(smw + 8192, 1);     // A_L2 over B1
    __syncthreads();

    // ---- layer 2: A_L2 @ smw+8192, B2 @ smw+16384 ----
    #pragma unroll
    for (int ks = 0; ks < 8; ks++) {
        #pragma unroll
        for (int mt = 0; mt < 2; mt++) {
            uint4 av = *(const uint4*)&smw[8192 + ((warp_m*2 + mt)*8 + ks)*128 + lane*4];
            #pragma unroll
            for (int nt = 0; nt < 8; nt++) {
                uint2 bv = *(const uint2*)&smw[16384 + ks*1024 + (warp_n*8 + nt)*64 + lane*2];
                mma16(acc[mt][nt], av.x, av.y, av.z, av.w, bv.x, bv.y);
            }
        }
    }

    // ---- maxpool epilogue (8 groups of 16 rows) ----
    #pragma unroll
    for (int mt = 0; mt < 2; mt++) {
        int gidx = tile*8 + warp_m*2 + mt;
        #pragma unroll
        for (int nt = 0; nt < 8; nt++) {
            int c = warp_n*64 + nt*8 + tig*2;
            float ga = sg[2][c], gb = sg[2][c+1];
            float ba = sb[2][c], bbv = sb[2][c+1];
            float ea = se[2][c], eb = se[2][c+1];
            float v0 = fmaxf(fmaf(ga, acc[mt][nt][0] + ba, ea), 0.0f);
            float v1 = fmaxf(fmaf(gb, acc[mt][nt][1] + bbv, eb), 0.0f);
            float v2 = fmaxf(fmaf(ga, acc[mt][nt][2] + ba, ea), 0.0f);
            float v3 = fmaxf(fmaf(gb, acc[mt][nt][3] + bbv, eb), 0.0f);
            float mA = fmaxf(v0, v2), mB = fmaxf(v1, v3);
            #pragma unroll
            for (int o = 4; o < 32; o <<= 1) {
                mA = fmaxf(mA, __shfl_xor_sync(0xffffffffu, mA, o));
                mB = fmaxf(mB, __shfl_xor_sync(0xffffffffu, mB, o));
            }
            if (grp == 0) {
                g_feat[(size_t)gidx*128 + c]     = mA;
                g_feat[(size_t)gidx*128 + c + 1] = mB;
            }
        }
    }
}

// ---------------- fused FC1+FC2+head, error-compensated fp16 (M=64, 512 threads, co-staged hi/lo) ----------------
// smem words: A_hi [0,4096), A_lo [4096,8192), B_hi [8192,16384), B_lo [16384,24576)  (96KB)
__global__ __launch_bounds__(512)
void fused_fc_kernel(const float* __restrict__ b1, const float* __restrict__ g1, const float* __restrict__ e1,
                     const float* __restrict__ b2, const float* __restrict__ g2, const float* __restrict__ e2,
                     const float* __restrict__ b3, const float* __restrict__ msz,
                     float* __restrict__ out) {
    extern __shared__ uint32_t smf[];
    uint32_t* A_hi = smf;
    uint32_t* A_lo = smf + 4096;
    uint32_t* B_hi = smf + 8192;
    uint32_t* B_lo = smf + 16384;
    __shared__ float sg1[128], sb1[128], se1[128], sg2[128], sb2[128], se2[128];
    __shared__ float sb3[128], sms[54];

    const int tid = threadIdx.x, lane = tid & 31, wid = tid >> 5;   // wid 0..15
    const int warp_m = wid >> 2, warp_n = wid & 3;   // warp_m 0..3 (m16 tile), warp_n 0..3 (n32 quarter)
    const int grp = lane >> 2, tig = lane & 3;
    const int row0 = blockIdx.x * 64;

    if (tid < 128) {
        sg1[tid] = g1[tid]; sb1[tid] = b1[tid]; se1[tid] = e1[tid];
        sg2[tid] = g2[tid]; sb2[tid] = b2[tid]; se2[tid] = e2[tid];
        sb3[tid] = (tid < OUTC) ? b3[tid] : 0.0f;
    } else if (tid < 182) {
        sms[tid - 128] = msz[tid - 128];
    }

    // fill A_hi / A_lo from g_feat: 64 rows, 8 threads/row (16 cols each)
    const int ar = tid >> 3, h = tid & 7;
    const int m_tile_f = ar >> 4;
    const int R = ar & 15;
    const int grpa = R & 7;
    const int rowhi = R >> 3;
    {
        const float4* frow4 = (const float4*)(g_feat + (size_t)(row0 + ar) * 128);
        #pragma unroll
        for (int j = 0; j < 4; j++) {
            float4 v = frow4[h*4 + j];
            int ktile = h >> 1;                  // c0 = h*16 + j*4 -> c0>>4 = h (j*4<16) ... recompute:
            int c0 = h*16 + j*4;
            ktile = c0 >> 4;
            int kp0 = (c0 & 15) >> 1;
            float hx = __half2float(__float2half_rn(v.x));
            float hy = __half2float(__float2half_rn(v.y));
            float hz = __half2float(__float2half_rn(v.z));
            float hw = __half2float(__float2half_rn(v.w));
            uint32_t* bH = A_hi + (m_tile_f*8 + ktile)*128;
            uint32_t* bL = A_lo + (m_tile_f*8 + ktile)*128;
            a16pair(bH, grpa, rowhi, kp0,     packh2(v.x, v.y));
            a16pair(bH, grpa, rowhi, kp0 + 1, packh2(v.z, v.w));
            a16pair(bL, grpa, rowhi, kp0,     packh2(v.x - hx, v.y - hy));
            a16pair(bL, grpa, rowhi, kp0 + 1, packh2(v.z - hz, v.w - hw));
        }
    }

    float acc[4][4];
    #pragma unroll
    for (int nt = 0; nt < 4; nt++)
        #pragma unroll
        for (int q = 0; q < 4; q++) acc[nt][q] = 0.0f;

    // co-stage hi and lo B matrices
    auto stage_pair = [&](const uint32_t* srcH, const uint32_t* srcL) {
        const uint4* sH = (const uint4*)srcH;
        const uint4* sL = (const uint4*)srcL;
        uint4* dH = (uint4*)B_hi;
        uint4* dL = (uint4*)B_lo;
        #pragma unroll
        for (int q = 0; q < 4; q++) {
            dH[tid + q*512] = sH[tid + q*512];
            dL[tid + q*512] = sL[tid + q*512];
        }
    };
    // one K=128 fp16 GEMM pass
    auto mmaF = [&](const uint32_t* Af, const uint32_t* Bf) {
        #pragma unroll
        for (int ks = 0; ks < 8; ks++) {
            uint4 av = *(const uint4*)&Af[(warp_m*8 + ks)*128 + lane*4];
            #pragma unroll
            for (int nt = 0; nt < 4; nt++) {
                uint2 bv = *(const uint2*)&Bf[ks*1024 + (warp_n*4 + nt)*64 + lane*2];
                mma16(acc[nt], av.x, av.y, av.z, av.w, bv.x, bv.y);
            }
        }
    };
    // compensated epilogue: relu6 affine -> fp16 hi/lo A-frags, zero acc
    auto epi_hilo = [&](const float* sgp, const float* sbp, const float* sep) {
        #pragma unroll
        for (int nt = 0; nt < 4; nt++) {
            int c = warp_n*32 + nt*8 + tig*2;
            float ga = sgp[c], gb = sgp[c+1], ba = sbp[c], bbv = sbp[c+1], ea = sep[c], eb = sep[c+1];
            float v0 = fminf(fmaxf(fmaf(ga, acc[nt][0] + ba, ea), 0.0f), 6.0f);
            float v1 = fminf(fmaxf(fmaf(gb, acc[nt][1] + bbv, eb), 0.0f), 6.0f);
            float v2 = fminf(fmaxf(fmaf(ga, acc[nt][2] + ba, ea), 0.0f), 6.0f);
            float v3 = fminf(fmaxf(fmaf(gb, acc[nt][3] + bbv, eb), 0.0f), 6.0f);
            float h0 = __half2float(__float2half_rn(v0));
            float h1 = __half2float(__float2half_rn(v1));
            float h2 = __half2float(__float2half_rn(v2));
            float h3 = __half2float(__float2half_rn(v3));
            int k_tile = warp_n*2 + (nt >> 1);
            uint32_t off = (warp_m*8 + k_tile)*128 + (grp*4 + tig)*4 + (nt & 1)*2;
            *(uint2*)&A_hi[off] = make_uint2(packh2(v0, v1), packh2(v2, v3));
            *(uint2*)&A_lo[off] = make_uint2(packh2(v0 - h0, v1 - h1), packh2(v2 - h2, v3 - h3));
            acc[nt][0] = 0.f; acc[nt][1] = 0.f; acc[nt][2] = 0.f; acc[nt][3] = 0.f;
        }
    };

    // ---- FC1 ----
    stage_pair(g_fh1h, g_fl1h);
    __syncthreads();
    mmaF(A_hi, B_hi);
    mmaF(A_lo, B_hi);
    mmaF(A_hi, B_lo);
    __syncthreads();
    epi_hilo(sg1, sb1, se1);
    stage_pair(g_fh2h, g_fl2h);
    __syncthreads();

    // ---- FC2 ----
    mmaF(A_hi, B_hi);
    mmaF(A_lo, B_hi);
    mmaF(A_hi, B_lo);
    __syncthreads();
    epi_hilo(sg2, sb2, se2);
    stage_pair(g_fh3h, g_fl3h);
    __syncthreads();

    // ---- head ----
    mmaF(A_hi, B_hi);
    mmaF(A_lo, B_hi);
    mmaF(A_hi, B_lo);

    // head scatter from accumulator frags
    const float HRS = (float)(3.14159265359 / 12.0);
    {
        int rA = row0 + warp_m*16 + grp;
        #pragma unroll
        for (int nt = 0; nt < 4; nt++) {
            int c0 = warp_n*32 + nt*8 + tig*2;
            #pragma unroll
            for (int q = 0; q < 4; q++) {
                int c = c0 + (q & 1);
                int r = (q < 2) ? rA : rA + 8;
                if (c >= OUTC) continue;
                float v = acc[nt][q] + sb3[c];
                if (c < 3)       out[O_CENTER + r*3 + c] = g_newxyz[r*3 + c] + v;
                else if (c < 5)  out[O_OBJ + r*2 + (c-3)] = v;
                else if (c < 17) out[O_HS + r*12 + (c-5)] = v;
                else if (c < 35) out[O_SS + r*18 + (c-17)] = v;
                else if (c < 47) { out[O_HRN + r*12 + (c-35)] = v; out[O_HR + r*12 + (c-35)] = v * HRS; }
                else if (c < 101){ int s = c - 47; out[O_SRN + r*54 + s] = v; out[O_SR + r*54 + s] = v * sms[s]; }
                else             out[O_SEM + r*18 + (c-101)] = v;
            }
        }
    }
}

// ---------------- launch ----------------
extern "C" void kernel_launch(void* const* d_in, const int* in_sizes, int n_in,
                              void* d_out, int out_size) {
    const float* xyz      = (const float*)d_in[0];
    const float* features = (const float*)d_in[1];
    const float* msz      = (const float*)d_in[2];
    const float* w0  = (const float*)d_in[3];
    const float* b0  = (const float*)d_in[4];
    const float* gm0 = (const float*)d_in[5];
    const float* be0 = (const float*)d_in[6];
    const float* wm1 = (const float*)d_in[7];
    const float* bm1 = (const float*)d_in[8];
    const float* gm1 = (const float*)d_in[9];
    const float* bem1= (const float*)d_in[10];
    const float* wm2 = (const float*)d_in[11];
    const float* bm2 = (const float*)d_in[12];
    const float* gm2 = (const float*)d_in[13];
    const float* bem2= (const float*)d_in[14];
    const float* w1  = (const float*)d_in[15];
    const float* b1  = (const float*)d_in[16];
    const float* g1  = (const float*)d_in[17];
    const float* be1 = (const float*)d_in[18];
    const float* w2  = (const float*)d_in[19];
    const float* b2  = (const float*)d_in[20];
    const float* g2  = (const float*)d_in[21];
    const float* be2 = (const float*)d_in[22];
    const float* w3  = (const float*)d_in[23];
    const float* b3  = (const float*)d_in[24];
    float* out = (float*)d_out;

    cudaFuncSetAttribute(fused_mlp_kernel, cudaFuncAttributeMaxDynamicSharedMemorySize, 98304);
    cudaFuncSetAttribute(fused_fc_kernel,  cudaFuncAttributeMaxDynamicSharedMemorySize, 98304);

    fps_prep_kernel<<<148, 128>>>(xyz, w0, wm1, wm2, w1, w2, w3, out);
    bq_kernel<<<BB, 1024>>>(xyz);
    fused_mlp_kernel<<<NROWS/128, 256, 98304>>>(xyz, features,
                                                b0, gm0, be0,
                                                bm1, gm1, bem1,
                                                bm2, gm2, bem2);
    fused_fc_kernel<<<NG/64, 512, 98304>>>(b1, g1, be1, b2, g2, be2, b3, msz, out);
}